// round 6
// baseline (speedup 1.0000x reference)
#include <cuda_runtime.h>
#include <math.h>

// Problem constants
#define B_    8
#define S_    1024
#define HID_  1024
#define H_    8
#define HD_   128
#define MD_   8
#define L_    3
#define M_    (B_*S_)      // 8192 rows
#define BH_   (B_*H_)      // 64 batched attention heads
#define EPS_  1e-7f
#define INV_SQRT_D 0.08838834764831845f   // 1/sqrt(128)

// ------------------------------------------------------------------
// Device-global scratch (allocation-free per harness rules)
// ------------------------------------------------------------------
__device__ float g_cur[(size_t)M_ * HID_];          //  32 MB
__device__ float g_qkv[(size_t)M_ * 3 * HID_];      //  96 MB
__device__ float g_Q[(size_t)BH_ * S_ * HD_];       //  32 MB (expmapped)
__device__ float g_Kf[(size_t)BH_ * S_ * HD_];      //  32 MB (expmapped)
__device__ float g_V[(size_t)BH_ * S_ * HD_];       //  32 MB
__device__ float g_P[(size_t)BH_ * S_ * S_];        // 256 MB scores/probs
__device__ float g_O[(size_t)M_ * HID_];            //  32 MB

// ------------------------------------------------------------------
// Copy x -> g_cur (float4 vectorized)
// ------------------------------------------------------------------
__global__ void copy_x_kernel(const float* __restrict__ x) {
    size_t i = (size_t)blockIdx.x * blockDim.x + threadIdx.x;
    ((float4*)g_cur)[i] = ((const float4*)x)[i];
}

// ------------------------------------------------------------------
// Generic SGEMM + bias:  C[M,N] = A[M,K] @ B[K,N] + bias[N]
// 128x128 tile, BK=8, 256 threads, 8x8 microtile.
// Requires M%128==0, N%128==0, K%8==0 (all satisfied here).
// ------------------------------------------------------------------
__global__ __launch_bounds__(256)
void sgemm_bias_kernel(const float* __restrict__ A, const float* __restrict__ Bm,
                       const float* __restrict__ bias, float* __restrict__ C,
                       int M, int N, int K)
{
    __shared__ float As[8][128];
    __shared__ float Bs[8][128];
    const int tid  = threadIdx.x;
    const int brow = blockIdx.y * 128;
    const int bcol = blockIdx.x * 128;
    const int a_r  = tid >> 1;            // 0..127
    const int a_c  = (tid & 1) * 4;       // 0 or 4
    const int b_r  = tid >> 5;            // 0..7
    const int b_c  = (tid & 31) * 4;      // 0..124
    const int tx   = tid & 15;
    const int ty   = tid >> 4;

    float acc[8][8];
    #pragma unroll
    for (int i = 0; i < 8; i++)
        #pragma unroll
        for (int j = 0; j < 8; j++) acc[i][j] = 0.f;

    for (int k0 = 0; k0 < K; k0 += 8) {
        float4 av = *(const float4*)&A[(size_t)(brow + a_r) * K + k0 + a_c];
        As[a_c + 0][a_r] = av.x;
        As[a_c + 1][a_r] = av.y;
        As[a_c + 2][a_r] = av.z;
        As[a_c + 3][a_r] = av.w;
        *(float4*)&Bs[b_r][b_c] = *(const float4*)&Bm[(size_t)(k0 + b_r) * N + bcol + b_c];
        __syncthreads();
        #pragma unroll
        for (int k = 0; k < 8; k++) {
            float ar[8], br[8];
            #pragma unroll
            for (int i = 0; i < 8; i++) ar[i] = As[k][ty * 8 + i];
            #pragma unroll
            for (int j = 0; j < 8; j++) br[j] = Bs[k][tx * 8 + j];
            #pragma unroll
            for (int i = 0; i < 8; i++)
                #pragma unroll
                for (int j = 0; j < 8; j++) acc[i][j] += ar[i] * br[j];
        }
        __syncthreads();
    }

    #pragma unroll
    for (int i = 0; i < 8; i++) {
        int r = brow + ty * 8 + i;
        #pragma unroll
        for (int j = 0; j < 8; j++) {
            int c = bcol + tx * 8 + j;
            C[(size_t)r * N + c] = acc[i][j] + bias[c];
        }
    }
}

// ------------------------------------------------------------------
// Split qkv [B,S,3,H,HD] into Q/K (expmap0 applied) and V,
// laid out as [B*H, S, HD]. One warp = one head vector (128 floats).
// blockIdx.x = b*S+s (8192), blockIdx.y = part (0=q,1=k,2=v), 256 threads.
// ------------------------------------------------------------------
__global__ void split_expmap_kernel() {
    const int bs   = blockIdx.x;
    const int p    = blockIdx.y;
    const int h    = threadIdx.x >> 5;
    const int lane = threadIdx.x & 31;
    const int b = bs >> 10;          // bs / S_
    const int s = bs & 1023;         // bs % S_

    const float4* src = (const float4*)(g_qkv + (size_t)bs * 3 * HID_ + p * HID_ + h * HD_);
    float4 v = src[lane];

    if (p < 2) {
        float ss = v.x * v.x + v.y * v.y + v.z * v.z + v.w * v.w;
        #pragma unroll
        for (int o = 16; o > 0; o >>= 1) ss += __shfl_xor_sync(0xffffffffu, ss, o);
        float n  = fmaxf(sqrtf(ss), EPS_);
        float sc = tanhf(n) / n;
        v.x *= sc; v.y *= sc; v.z *= sc; v.w *= sc;
    }
    float* dst_base = (p == 0) ? g_Q : ((p == 1) ? g_Kf : g_V);
    float4* dst = (float4*)(dst_base + ((size_t)(b * H_ + h) * S_ + s) * HD_);
    dst[lane] = v;
}

// ------------------------------------------------------------------
// Batched scores: P[z] = (Qf[z] @ Kf[z]^T) * inv_sqrt_d
// z = blockIdx.z (64), M=N=1024, K=128. Same 128x128 tiling;
// both operands loaded with the A-pattern (both are [S,HD] row-major).
// ------------------------------------------------------------------
__global__ __launch_bounds__(256)
void scores_kernel() {
    const int z = blockIdx.z;
    const float* A  = g_Q  + (size_t)z * S_ * HD_;
    const float* Km = g_Kf + (size_t)z * S_ * HD_;
    float*       C  = g_P  + (size_t)z * S_ * S_;

    __shared__ float As[8][128];
    __shared__ float Bs[8][128];
    const int tid  = threadIdx.x;
    const int brow = blockIdx.y * 128;
    const int bcol = blockIdx.x * 128;
    const int lr   = tid >> 1;
    const int lc   = (tid & 1) * 4;
    const int tx   = tid & 15;
    const int ty   = tid >> 4;

    float acc[8][8];
    #pragma unroll
    for (int i = 0; i < 8; i++)
        #pragma unroll
        for (int j = 0; j < 8; j++) acc[i][j] = 0.f;

    for (int k0 = 0; k0 < HD_; k0 += 8) {
        float4 av = *(const float4*)&A [(size_t)(brow + lr) * HD_ + k0 + lc];
        As[lc + 0][lr] = av.x; As[lc + 1][lr] = av.y;
        As[lc + 2][lr] = av.z; As[lc + 3][lr] = av.w;
        float4 bv = *(const float4*)&Km[(size_t)(bcol + lr) * HD_ + k0 + lc];
        Bs[lc + 0][lr] = bv.x; Bs[lc + 1][lr] = bv.y;
        Bs[lc + 2][lr] = bv.z; Bs[lc + 3][lr] = bv.w;
        __syncthreads();
        #pragma unroll
        for (int k = 0; k < 8; k++) {
            float ar[8], br[8];
            #pragma unroll
            for (int i = 0; i < 8; i++) ar[i] = As[k][ty * 8 + i];
            #pragma unroll
            for (int j = 0; j < 8; j++) br[j] = Bs[k][tx * 8 + j];
            #pragma unroll
            for (int i = 0; i < 8; i++)
                #pragma unroll
                for (int j = 0; j < 8; j++) acc[i][j] += ar[i] * br[j];
        }
        __syncthreads();
    }

    #pragma unroll
    for (int i = 0; i < 8; i++) {
        int r = brow + ty * 8 + i;
        #pragma unroll
        for (int j = 0; j < 8; j++)
            C[(size_t)r * S_ + bcol + tx * 8 + j] = acc[i][j] * INV_SQRT_D;
    }
}

// ------------------------------------------------------------------
// Row softmax over g_P: 64*1024 rows of 1024. One block per row.
// ------------------------------------------------------------------
__global__ void softmax_kernel() {
    float* row = g_P + (size_t)blockIdx.x * S_;
    const int tid = threadIdx.x;
    float4 v = ((float4*)row)[tid];

    __shared__ float red[256];
    float m = fmaxf(fmaxf(v.x, v.y), fmaxf(v.z, v.w));
    red[tid] = m; __syncthreads();
    for (int s = 128; s > 0; s >>= 1) {
        if (tid < s) red[tid] = fmaxf(red[tid], red[tid + s]);
        __syncthreads();
    }
    m = red[0]; __syncthreads();

    v.x = expf(v.x - m); v.y = expf(v.y - m);
    v.z = expf(v.z - m); v.w = expf(v.w - m);
    float sum = v.x + v.y + v.z + v.w;
    red[tid] = sum; __syncthreads();
    for (int s = 128; s > 0; s >>= 1) {
        if (tid < s) red[tid] += red[tid + s];
        __syncthreads();
    }
    float inv = 1.0f / red[0];
    v.x *= inv; v.y *= inv; v.z *= inv; v.w *= inv;
    ((float4*)row)[tid] = v;
}

// ------------------------------------------------------------------
// Batched PV: O[z] = P[z] @ V[z], M=1024, N=128, K=1024.
// Epilogue scatters directly into [B,S,HID] layout (g_O).
// ------------------------------------------------------------------
__global__ __launch_bounds__(256)
void pv_kernel() {
    const int z = blockIdx.z;
    const int b = z >> 3, h = z & 7;
    const float* A = g_P + (size_t)z * S_ * S_;
    const float* V = g_V + (size_t)z * S_ * HD_;

    __shared__ float As[8][128];
    __shared__ float Bs[8][128];
    const int tid  = threadIdx.x;
    const int brow = blockIdx.y * 128;
    const int a_r  = tid >> 1;
    const int a_c  = (tid & 1) * 4;
    const int b_r  = tid >> 5;
    const int b_c  = (tid & 31) * 4;
    const int tx   = tid & 15;
    const int ty   = tid >> 4;

    float acc[8][8];
    #pragma unroll
    for (int i = 0; i < 8; i++)
        #pragma unroll
        for (int j = 0; j < 8; j++) acc[i][j] = 0.f;

    for (int k0 = 0; k0 < S_; k0 += 8) {
        float4 av = *(const float4*)&A[(size_t)(brow + a_r) * S_ + k0 + a_c];
        As[a_c + 0][a_r] = av.x; As[a_c + 1][a_r] = av.y;
        As[a_c + 2][a_r] = av.z; As[a_c + 3][a_r] = av.w;
        *(float4*)&Bs[b_r][b_c] = *(const float4*)&V[(size_t)(k0 + b_r) * HD_ + b_c];
        __syncthreads();
        #pragma unroll
        for (int k = 0; k < 8; k++) {
            float ar[8], br[8];
            #pragma unroll
            for (int i = 0; i < 8; i++) ar[i] = As[k][ty * 8 + i];
            #pragma unroll
            for (int j = 0; j < 8; j++) br[j] = Bs[k][tx * 8 + j];
            #pragma unroll
            for (int i = 0; i < 8; i++)
                #pragma unroll
                for (int j = 0; j < 8; j++) acc[i][j] += ar[i] * br[j];
        }
        __syncthreads();
    }

    #pragma unroll
    for (int i = 0; i < 8; i++) {
        int s = brow + ty * 8 + i;
        #pragma unroll
        for (int j = 0; j < 8; j++) {
            int d = tx * 8 + j;
            g_O[((size_t)b * S_ + s) * HID_ + h * HD_ + d] = acc[i][j];
        }
    }
}

// ------------------------------------------------------------------
// Manifold update (fused): m = O_row @ W_pinv + b_pinv  (1024 -> 8)
//                          cur_row += m @ W_attn[l] + b_attn[l]
// One block (256 thr, 8 warps) per row; warp w computes m[w].
// ------------------------------------------------------------------
__global__ void update_kernel(const float* __restrict__ W_pinv,
                              const float* __restrict__ b_pinv,
                              const float* __restrict__ Wa,
                              const float* __restrict__ ba)
{
    const int row  = blockIdx.x;
    const int tid  = threadIdx.x;
    const int warp = tid >> 5;
    const int lane = tid & 31;
    const float* orow = g_O + (size_t)row * HID_;

    __shared__ float m[MD_];
    float acc = 0.f;
    for (int i = lane; i < HID_; i += 32)
        acc += orow[i] * W_pinv[i * MD_ + warp];
    #pragma unroll
    for (int o = 16; o > 0; o >>= 1) acc += __shfl_xor_sync(0xffffffffu, acc, o);
    if (lane == 0) m[warp] = acc + b_pinv[warp];
    __syncthreads();

    float mv[MD_];
    #pragma unroll
    for (int j = 0; j < MD_; j++) mv[j] = m[j];

    #pragma unroll
    for (int t = 0; t < HID_ / 256; t++) {
        int col = tid + t * 256;
        float u = ba[col];
        #pragma unroll
        for (int j = 0; j < MD_; j++) u += mv[j] * Wa[j * HID_ + col];
        g_cur[(size_t)row * HID_ + col] += u;
    }
}

// ------------------------------------------------------------------
// Host launcher (graph-capturable: kernels only, default stream)
// ------------------------------------------------------------------
extern "C" void kernel_launch(void* const* d_in, const int* in_sizes, int n_in,
                              void* d_out, int out_size)
{
    const float* x      = (const float*)d_in[0];
    const float* W_qkv  = (const float*)d_in[1];
    const float* b_qkv  = (const float*)d_in[2];
    const float* W_pinv = (const float*)d_in[3];
    const float* b_pinv = (const float*)d_in[4];
    const float* W_attn = (const float*)d_in[5];
    const float* b_attn = (const float*)d_in[6];
    const float* W_out  = (const float*)d_in[7];
    const float* b_out  = (const float*)d_in[8];
    float* out = (float*)d_out;

    float *curp = nullptr, *qkvp = nullptr;
    cudaGetSymbolAddress((void**)&curp, g_cur);
    cudaGetSymbolAddress((void**)&qkvp, g_qkv);

    // g_cur = x
    copy_x_kernel<<<(M_ * HID_) / 4 / 256, 256>>>(x);

    for (int l = 0; l < L_; ++l) {
        // qkv = cur @ W_qkv + b_qkv
        sgemm_bias_kernel<<<dim3(3 * HID_ / 128, M_ / 128), 256>>>(
            curp, W_qkv, b_qkv, qkvp, M_, 3 * HID_, HID_);

        // split into heads, apply expmap0 to q,k
        split_expmap_kernel<<<dim3(M_, 3), 256>>>();

        // scores = Qf @ Kf^T * inv_sqrt_d   (batch 64)
        scores_kernel<<<dim3(S_ / 128, S_ / 128, BH_), 256>>>();

        // row softmax
        softmax_kernel<<<BH_ * S_, 256>>>();

        // O = P @ V, reassembled into [B,S,HID]
        pv_kernel<<<dim3(1, S_ / 128, BH_), 256>>>();

        // cur += (O @ W_pinv + b_pinv) @ W_attn[l] + b_attn[l]
        update_kernel<<<M_, 256>>>(W_pinv, b_pinv,
                                   W_attn + (size_t)l * MD_ * HID_,
                                   b_attn + (size_t)l * HID_);
    }

    // out = cur @ W_out + b_out
    sgemm_bias_kernel<<<dim3(HID_ / 128, M_ / 128), 256>>>(
        curp, W_out, b_out, out, M_, HID_, HID_);
}

// round 8
// speedup vs baseline: 3.8012x; 3.8012x over previous
#include <cuda_runtime.h>
#include <cuda_bf16.h>
#include <cstdint>
#include <math.h>

#define B_    8
#define S_    1024
#define HID_  1024
#define H_    8
#define HD_   128
#define MD_   8
#define L_    3
#define M_    (B_*S_)
#define BH_   (B_*H_)
#define EPS_  1e-7f
#define INV_SQRT_D 0.08838834764831845f

// ---------------- PTX helpers (plain sm_80+ features only) ----------------
__device__ __forceinline__ uint32_t smem_u32(const void* p){
    uint32_t a;
    asm("{ .reg .u64 t; cvta.to.shared.u64 t, %1; cvt.u32.u64 %0, t; }" : "=r"(a) : "l"(p));
    return a;
}
#define CPA(sa, gp) \
    asm volatile("cp.async.cg.shared.global [%0], [%1], 16;" \
        :: "r"(sa), "l"(__cvta_generic_to_global((const void*)(gp))) : "memory")
#define CP_COMMIT() asm volatile("cp.async.commit_group;" ::: "memory")
#define CP_WAIT1()  asm volatile("cp.async.wait_group 1;" ::: "memory")
#define CP_WAIT0()  asm volatile("cp.async.wait_group 0;" ::: "memory")

#define LDSM4(r, addr) \
    asm volatile("ldmatrix.sync.aligned.m8n8.x4.shared.b16 {%0,%1,%2,%3}, [%4];" \
        : "=r"((r)[0]), "=r"((r)[1]), "=r"((r)[2]), "=r"((r)[3]) : "r"(addr))

#define MMA_B16(c, a0,a1,a2,a3, b0,b1) \
    asm volatile("mma.sync.aligned.m16n8k16.row.col.f32.bf16.bf16.f32 " \
        "{%0,%1,%2,%3}, {%4,%5,%6,%7}, {%8,%9}, {%0,%1,%2,%3};" \
        : "+f"((c)[0]), "+f"((c)[1]), "+f"((c)[2]), "+f"((c)[3]) \
        : "r"(a0), "r"(a1), "r"(a2), "r"(a3), "r"(b0), "r"(b1))

// ---------------- scratch ----------------
__device__ float          g_cur [(size_t)M_ * HID_];
__device__ __nv_bfloat16  g_curh[(size_t)M_ * HID_];
__device__ __nv_bfloat16  g_curl[(size_t)M_ * HID_];
__device__ float          g_qkv [(size_t)M_ * 3 * HID_];
__device__ __nv_bfloat16  g_Wqh [(size_t)3 * HID_ * HID_];   // W_qkv^T bf16 [3072,1024]
__device__ __nv_bfloat16  g_Wql [(size_t)3 * HID_ * HID_];   // (unused lo; kept by wt_kernel)
__device__ __nv_bfloat16  g_Woh [(size_t)HID_ * HID_];       // W_out^T hi
__device__ __nv_bfloat16  g_Wol [(size_t)HID_ * HID_];       // W_out^T lo
__device__ __nv_bfloat16  g_Qb  [(size_t)BH_ * S_ * HD_];
__device__ __nv_bfloat16  g_Kb  [(size_t)BH_ * S_ * HD_];
__device__ __nv_bfloat16  g_Vt  [(size_t)BH_ * HD_ * S_];    // V^T [z, d, s]
__device__ __nv_bfloat16  g_Pb  [(size_t)BH_ * S_ * S_];     // scores/probs bf16
__device__ float          g_O   [(size_t)M_ * HID_];

// ==================================================================
// MMA core: acc[4][4][4] += A[128,K] @ B[128,K]^T  (bf16 in, fp32 acc)
// NT=3 adds hi/lo cross terms (Ah*Bl + Al*Bh).
// SMEM tile: 128 rows x 80B (64B data + 16B pad) -> conflict-free ldmatrix.
// Double-buffered cp.async, BK=32.
// ==================================================================
template<int NT>
__device__ __forceinline__ void mma_core(
    float (&acc)[4][4][4],
    const __nv_bfloat16* __restrict__ Ah, const __nv_bfloat16* __restrict__ Al,
    const __nv_bfloat16* __restrict__ Bh, const __nv_bfloat16* __restrict__ Bl,
    int ldA, int ldB, int K, char* smem)
{
    constexpr int TILE = 128 * 80;               // 10240 B
    constexpr int NS   = (NT == 3) ? 4 : 2;      // tiles per stage
    constexpr int STG  = NS * TILE;
    const int tid  = threadIdx.x;
    const int lane = tid & 31, warp = tid >> 5;
    const int wm = (warp >> 2) * 64;             // warp m-offset (0/64)
    const int wn = (warp & 3) * 32;              // warp n-offset (0..96)
    const uint32_t sb = smem_u32(smem);

    auto issue = [&](int buf, int k0) {
        #pragma unroll
        for (int i = 0; i < 2; i++) {
            int q = tid + i * 256;               // 512 chunks of 16B per tile
            int r = q >> 2, c = q & 3;
            uint32_t sa = sb + buf * STG + r * 80 + c * 16;
            CPA(sa,                              Ah + (size_t)r * ldA + k0 + c * 8);
            CPA(sa + (NT == 3 ? 2 : 1) * TILE,   Bh + (size_t)r * ldB + k0 + c * 8);
            if (NT == 3) {
                CPA(sa + TILE,                   Al + (size_t)r * ldA + k0 + c * 8);
                CPA(sa + 3 * TILE,               Bl + (size_t)r * ldB + k0 + c * 8);
            }
        }
        CP_COMMIT();
    };

    issue(0, 0);
    const int T = K / 32;
    for (int kt = 0; kt < T; kt++) {
        const int buf = kt & 1;
        if (kt + 1 < T) { issue(buf ^ 1, (kt + 1) * 32); CP_WAIT1(); }
        else            { CP_WAIT0(); }
        __syncthreads();
        const uint32_t ab = sb + buf * STG;
        const uint32_t bb = ab + (NT == 3 ? 2 : 1) * TILE;
        #pragma unroll
        for (int kk = 0; kk < 2; kk++) {
            // shared ldmatrix lane-address offset (rows lane&15, 16B col by lane>>4)
            const uint32_t roff = (uint32_t)(lane & 15) * 80 + (2 * kk + (lane >> 4)) * 16;
            uint32_t bh[8], bl[8];
            LDSM4(bh,     bb + (uint32_t)wn * 80 + roff);
            LDSM4(bh + 4, bb + (uint32_t)(wn + 16) * 80 + roff);
            if (NT == 3) {
                LDSM4(bl,     bb + TILE + (uint32_t)wn * 80 + roff);
                LDSM4(bl + 4, bb + TILE + (uint32_t)(wn + 16) * 80 + roff);
            }
            #pragma unroll
            for (int mi = 0; mi < 4; mi++) {
                uint32_t ah[4], al[4];
                const uint32_t abase = ab + (uint32_t)(wm + mi * 16) * 80 + roff;
                LDSM4(ah, abase);
                if (NT == 3) LDSM4(al, abase + TILE);
                #pragma unroll
                for (int ni = 0; ni < 4; ni++) {
                    const int p = (ni >> 1) * 4, s = ni & 1;
                    uint32_t b0 = bh[p + s], b1 = bh[p + 2 + s];
                    MMA_B16(acc[mi][ni], ah[0], ah[1], ah[2], ah[3], b0, b1);
                    if (NT == 3) {
                        uint32_t d0 = bl[p + s], d1 = bl[p + 2 + s];
                        MMA_B16(acc[mi][ni], ah[0], ah[1], ah[2], ah[3], d0, d1);
                        MMA_B16(acc[mi][ni], al[0], al[1], al[2], al[3], b0, b1);
                    }
                }
            }
        }
        __syncthreads();
    }
}

#define ACC_ZERO(acc) \
    _Pragma("unroll") for (int _i = 0; _i < 4; _i++) \
    _Pragma("unroll") for (int _j = 0; _j < 4; _j++) \
    _Pragma("unroll") for (int _k = 0; _k < 4; _k++) (acc)[_i][_j][_k] = 0.f;

// ---- QKV GEMM (single bf16): C[M,N] = A@B^T + bias ----
__global__ __launch_bounds__(256)
void gemm_h_kernel(const __nv_bfloat16* __restrict__ A, const __nv_bfloat16* __restrict__ B,
                   const float* __restrict__ bias, float* __restrict__ C, int N, int K)
{
    extern __shared__ char smem[];
    const int brow = blockIdx.y * 128, bcol = blockIdx.x * 128;
    float acc[4][4][4]; ACC_ZERO(acc);
    mma_core<1>(acc, A + (size_t)brow * K, nullptr, B + (size_t)bcol * K, nullptr, K, K, K, smem);
    const int lane = threadIdx.x & 31, warp = threadIdx.x >> 5;
    const int wm = (warp >> 2) * 64, wn = (warp & 3) * 32;
    #pragma unroll
    for (int mi = 0; mi < 4; mi++)
        #pragma unroll
        for (int ni = 0; ni < 4; ni++) {
            int r = brow + wm + mi * 16 + (lane >> 2);
            int c = bcol + wn + ni * 8 + (lane & 3) * 2;
            float bx = bias[c], by = bias[c + 1];
            *(float2*)&C[(size_t)r * N + c]       = make_float2(acc[mi][ni][0] + bx, acc[mi][ni][1] + by);
            *(float2*)&C[(size_t)(r + 8) * N + c] = make_float2(acc[mi][ni][2] + bx, acc[mi][ni][3] + by);
        }
}

// ---- out-proj GEMM (hi/lo split): C = (Ah+Al)@(Bh+Bl)^T + bias ----
__global__ __launch_bounds__(256)
void gemm3_kernel(const __nv_bfloat16* __restrict__ Ah, const __nv_bfloat16* __restrict__ Al,
                  const __nv_bfloat16* __restrict__ Bh, const __nv_bfloat16* __restrict__ Bl,
                  const float* __restrict__ bias, float* __restrict__ C, int N, int K)
{
    extern __shared__ char smem[];
    const int brow = blockIdx.y * 128, bcol = blockIdx.x * 128;
    float acc[4][4][4]; ACC_ZERO(acc);
    mma_core<3>(acc, Ah + (size_t)brow * K, Al + (size_t)brow * K,
                     Bh + (size_t)bcol * K, Bl + (size_t)bcol * K, K, K, K, smem);
    const int lane = threadIdx.x & 31, warp = threadIdx.x >> 5;
    const int wm = (warp >> 2) * 64, wn = (warp & 3) * 32;
    #pragma unroll
    for (int mi = 0; mi < 4; mi++)
        #pragma unroll
        for (int ni = 0; ni < 4; ni++) {
            int r = brow + wm + mi * 16 + (lane >> 2);
            int c = bcol + wn + ni * 8 + (lane & 3) * 2;
            float bx = bias[c], by = bias[c + 1];
            *(float2*)&C[(size_t)r * N + c]       = make_float2(acc[mi][ni][0] + bx, acc[mi][ni][1] + by);
            *(float2*)&C[(size_t)(r + 8) * N + c] = make_float2(acc[mi][ni][2] + bx, acc[mi][ni][3] + by);
        }
}

// ---- scores: Pb[z] = bf16((Qb@Kb^T) * inv_sqrt_d). grid (8,8,64) ----
__global__ __launch_bounds__(256)
void scores_mma_kernel()
{
    extern __shared__ char smem[];
    const int z = blockIdx.z, brow = blockIdx.y * 128, bcol = blockIdx.x * 128;
    float acc[4][4][4]; ACC_ZERO(acc);
    mma_core<1>(acc, g_Qb + ((size_t)z * S_ + brow) * HD_, nullptr,
                     g_Kb + ((size_t)z * S_ + bcol) * HD_, nullptr, HD_, HD_, HD_, smem);
    const int lane = threadIdx.x & 31, warp = threadIdx.x >> 5;
    const int wm = (warp >> 2) * 64, wn = (warp & 3) * 32;
    __nv_bfloat16* P = g_Pb + (size_t)z * S_ * S_;
    #pragma unroll
    for (int mi = 0; mi < 4; mi++)
        #pragma unroll
        for (int ni = 0; ni < 4; ni++) {
            int r = brow + wm + mi * 16 + (lane >> 2);
            int c = bcol + wn + ni * 8 + (lane & 3) * 2;
            *(__nv_bfloat162*)&P[(size_t)r * S_ + c] =
                __floats2bfloat162_rn(acc[mi][ni][0] * INV_SQRT_D, acc[mi][ni][1] * INV_SQRT_D);
            *(__nv_bfloat162*)&P[(size_t)(r + 8) * S_ + c] =
                __floats2bfloat162_rn(acc[mi][ni][2] * INV_SQRT_D, acc[mi][ni][3] * INV_SQRT_D);
        }
}

// ---- PV: O = Pb @ Vt^T, scattered into [B,S,HID]. grid (1,8,64) ----
__global__ __launch_bounds__(256)
void pv_mma_kernel()
{
    extern __shared__ char smem[];
    const int z = blockIdx.z, b = z >> 3, h = z & 7;
    const int brow = blockIdx.y * 128;
    float acc[4][4][4]; ACC_ZERO(acc);
    mma_core<1>(acc, g_Pb + (size_t)z * S_ * S_ + (size_t)brow * S_, nullptr,
                     g_Vt + (size_t)z * HD_ * S_, nullptr, S_, S_, S_, smem);
    const int lane = threadIdx.x & 31, warp = threadIdx.x >> 5;
    const int wm = (warp >> 2) * 64, wn = (warp & 3) * 32;
    #pragma unroll
    for (int mi = 0; mi < 4; mi++)
        #pragma unroll
        for (int ni = 0; ni < 4; ni++) {
            int r = brow + wm + mi * 16 + (lane >> 2);
            int c = wn + ni * 8 + (lane & 3) * 2;
            *(float2*)&g_O[(size_t)(b * S_ + r) * HID_ + h * HD_ + c] =
                make_float2(acc[mi][ni][0], acc[mi][ni][1]);
            *(float2*)&g_O[(size_t)(b * S_ + r + 8) * HID_ + h * HD_ + c] =
                make_float2(acc[mi][ni][2], acc[mi][ni][3]);
        }
}

// ---------------- small kernels ----------------
__device__ __forceinline__ void split_store(float v, __nv_bfloat16* h, __nv_bfloat16* l, size_t i){
    __nv_bfloat16 hi = __float2bfloat16(v);
    h[i] = hi;
    l[i] = __float2bfloat16(v - __bfloat162float(hi));
}

__global__ void copy_x_kernel(const float* __restrict__ x){
    size_t i = (size_t)blockIdx.x * blockDim.x + threadIdx.x;
    float4 v = ((const float4*)x)[i];
    ((float4*)g_cur)[i] = v;
    size_t e = i * 4;
    split_store(v.x, g_curh, g_curl, e + 0);
    split_store(v.y, g_curh, g_curl, e + 1);
    split_store(v.z, g_curh, g_curl, e + 2);
    split_store(v.w, g_curh, g_curl, e + 3);
}

// transpose W[K,N] fp32 -> bf16 hi/lo [N,K]
__global__ void wt_kernel(const float* __restrict__ src,
                          __nv_bfloat16* __restrict__ dh, __nv_bfloat16* __restrict__ dl,
                          int K, int N)
{
    __shared__ float t[32][33];
    const int n0 = blockIdx.x * 32, k0 = blockIdx.y * 32;
    const int tx = threadIdx.x, ty = threadIdx.y;
    for (int i = ty; i < 32; i += 8)
        t[i][tx] = src[(size_t)(k0 + i) * N + n0 + tx];
    __syncthreads();
    for (int i = ty; i < 32; i += 8)
        split_store(t[tx][i], dh, dl, (size_t)(n0 + i) * K + k0 + tx);
}

// q/k heads with expmap0 -> bf16 [z,s,d]. grid (8192,2), 256 thr
__global__ void split_expmap_kernel(){
    const int bs = blockIdx.x, p = blockIdx.y;
    const int h = threadIdx.x >> 5, lane = threadIdx.x & 31;
    const int b = bs >> 10, s = bs & 1023;
    const float4* src = (const float4*)(g_qkv + (size_t)bs * 3 * HID_ + p * HID_ + h * HD_);
    float4 v = src[lane];
    float ss = v.x * v.x + v.y * v.y + v.z * v.z + v.w * v.w;
    #pragma unroll
    for (int o = 16; o > 0; o >>= 1) ss += __shfl_xor_sync(0xffffffffu, ss, o);
    float n  = fmaxf(sqrtf(ss), EPS_);
    float sc = tanhf(n) / n;
    __nv_bfloat162* d2 = (__nv_bfloat162*)((p ? g_Kb : g_Qb) + ((size_t)(b * H_ + h) * S_ + s) * HD_);
    d2[lane * 2 + 0] = __floats2bfloat162_rn(v.x * sc, v.y * sc);
    d2[lane * 2 + 1] = __floats2bfloat162_rn(v.z * sc, v.w * sc);
}

// V part of qkv fp32 -> Vt bf16 [z, d, s]. grid (32,4,64), block (32,8)
__global__ void vt_kernel(){
    __shared__ float t[32][33];
    const int z = blockIdx.z, s0 = blockIdx.x * 32, d0 = blockIdx.y * 32;
    const int b = z >> 3, h = z & 7;
    const int tx = threadIdx.x, ty = threadIdx.y;
    for (int i = ty; i < 32; i += 8)
        t[i][tx] = g_qkv[(size_t)(b * S_ + s0 + i) * (3 * HID_) + 2 * HID_ + h * HD_ + d0 + tx];
    __syncthreads();
    for (int i = ty; i < 32; i += 8)
        g_Vt[(size_t)z * HD_ * S_ + (size_t)(d0 + i) * S_ + s0 + tx] = __float2bfloat16(t[tx][i]);
}

// softmax in place on bf16 rows of 1024
__global__ void softmax_kernel(){
    __nv_bfloat162* r2 = (__nv_bfloat162*)(g_Pb + (size_t)blockIdx.x * S_);
    const int tid = threadIdx.x;
    __nv_bfloat162 a = r2[tid * 2], b2 = r2[tid * 2 + 1];
    float v0 = __bfloat162float(a.x),  v1 = __bfloat162float(a.y);
    float v2 = __bfloat162float(b2.x), v3 = __bfloat162float(b2.y);
    __shared__ float red[256];
    float m = fmaxf(fmaxf(v0, v1), fmaxf(v2, v3));
    red[tid] = m; __syncthreads();
    for (int s = 128; s > 0; s >>= 1) { if (tid < s) red[tid] = fmaxf(red[tid], red[tid + s]); __syncthreads(); }
    m = red[0]; __syncthreads();
    v0 = expf(v0 - m); v1 = expf(v1 - m); v2 = expf(v2 - m); v3 = expf(v3 - m);
    red[tid] = v0 + v1 + v2 + v3; __syncthreads();
    for (int s = 128; s > 0; s >>= 1) { if (tid < s) red[tid] += red[tid + s]; __syncthreads(); }
    float inv = 1.0f / red[0];
    r2[tid * 2]     = __floats2bfloat162_rn(v0 * inv, v1 * inv);
    r2[tid * 2 + 1] = __floats2bfloat162_rn(v2 * inv, v3 * inv);
}

// cur += (O @ W_pinv + b_pinv) @ Wa + ba ; refresh hi/lo
__global__ void update_kernel(const float* __restrict__ W_pinv, const float* __restrict__ b_pinv,
                              const float* __restrict__ Wa, const float* __restrict__ ba)
{
    const int row = blockIdx.x, tid = threadIdx.x;
    const int warp = tid >> 5, lane = tid & 31;
    const float* orow = g_O + (size_t)row * HID_;
    __shared__ float m[MD_];
    float acc = 0.f;
    for (int i = lane; i < HID_; i += 32)
        acc += orow[i] * W_pinv[i * MD_ + warp];
    #pragma unroll
    for (int o = 16; o > 0; o >>= 1) acc += __shfl_xor_sync(0xffffffffu, acc, o);
    if (lane == 0) m[warp] = acc + b_pinv[warp];
    __syncthreads();
    float mv[MD_];
    #pragma unroll
    for (int j = 0; j < MD_; j++) mv[j] = m[j];
    #pragma unroll
    for (int t = 0; t < HID_ / 256; t++) {
        int col = tid + t * 256;
        float u = ba[col];
        #pragma unroll
        for (int j = 0; j < MD_; j++) u += mv[j] * Wa[j * HID_ + col];
        size_t idx = (size_t)row * HID_ + col;
        float nc = g_cur[idx] + u;
        g_cur[idx] = nc;
        split_store(nc, g_curh, g_curl, idx);
    }
}

// ---------------- launcher ----------------
extern "C" void kernel_launch(void* const* d_in, const int* in_sizes, int n_in,
                              void* d_out, int out_size)
{
    const float* x      = (const float*)d_in[0];
    const float* W_qkv  = (const float*)d_in[1];
    const float* b_qkv  = (const float*)d_in[2];
    const float* W_pinv = (const float*)d_in[3];
    const float* b_pinv = (const float*)d_in[4];
    const float* W_attn = (const float*)d_in[5];
    const float* b_attn = (const float*)d_in[6];
    const float* W_out  = (const float*)d_in[7];
    const float* b_out  = (const float*)d_in[8];
    float* out = (float*)d_out;

    const int SM1 = 2 * 2 * 128 * 80;   // 40960 B (NT=1)
    const int SM3 = 2 * 4 * 128 * 80;   // 81920 B (NT=3)
    cudaFuncSetAttribute(gemm_h_kernel,     cudaFuncAttributeMaxDynamicSharedMemorySize, SM1);
    cudaFuncSetAttribute(gemm3_kernel,      cudaFuncAttributeMaxDynamicSharedMemorySize, SM3);
    cudaFuncSetAttribute(scores_mma_kernel, cudaFuncAttributeMaxDynamicSharedMemorySize, SM1);
    cudaFuncSetAttribute(pv_mma_kernel,     cudaFuncAttributeMaxDynamicSharedMemorySize, SM1);

    float *qkvp = nullptr;
    __nv_bfloat16 *curh = nullptr, *curl = nullptr, *wqh = nullptr, *wql = nullptr,
                  *woh = nullptr, *wol = nullptr;
    cudaGetSymbolAddress((void**)&qkvp, g_qkv);
    cudaGetSymbolAddress((void**)&curh, g_curh);
    cudaGetSymbolAddress((void**)&curl, g_curl);
    cudaGetSymbolAddress((void**)&wqh,  g_Wqh);
    cudaGetSymbolAddress((void**)&wql,  g_Wql);
    cudaGetSymbolAddress((void**)&woh,  g_Woh);
    cudaGetSymbolAddress((void**)&wol,  g_Wol);

    copy_x_kernel<<<(M_ * HID_) / 4 / 256, 256>>>(x);
    wt_kernel<<<dim3(3 * HID_ / 32, HID_ / 32), dim3(32, 8)>>>(W_qkv, wqh, wql, HID_, 3 * HID_);
    wt_kernel<<<dim3(HID_ / 32, HID_ / 32), dim3(32, 8)>>>(W_out, woh, wol, HID_, HID_);

    for (int l = 0; l < L_; ++l) {
        // qkv = cur @ W_qkv + b_qkv   (single bf16 — attention path is damped)
        gemm_h_kernel<<<dim3(3 * HID_ / 128, M_ / 128), 256, SM1>>>(
            curh, wqh, b_qkv, qkvp, 3 * HID_, HID_);
        split_expmap_kernel<<<dim3(M_, 2), 256>>>();
        vt_kernel<<<dim3(32, 4, BH_), dim3(32, 8)>>>();
        scores_mma_kernel<<<dim3(8, 8, BH_), 256, SM1>>>();
        softmax_kernel<<<BH_ * S_, 256>>>();
        pv_mma_kernel<<<dim3(1, 8, BH_), 256, SM1>>>();
        update_kernel<<<M_, 256>>>(W_pinv, b_pinv,
                                   W_attn + (size_t)l * MD_ * HID_,
                                   b_attn + (size_t)l * HID_);
    }

    // out = cur @ W_out + b_out   (hi/lo split — full-magnitude residual)
    gemm3_kernel<<<dim3(HID_ / 128, M_ / 128), 256, SM3>>>(
        curh, curl, woh, wol, b_out, out, HID_, HID_);
}

// round 10
// speedup vs baseline: 5.4033x; 1.4215x over previous
#include <cuda_runtime.h>
#include <cuda_bf16.h>
#include <cstdint>
#include <math.h>

#define B_    8
#define S_    1024
#define HID_  1024
#define H_    8
#define HD_   128
#define MD_   8
#define L_    3
#define M_    (B_*S_)
#define BH_   (B_*H_)
#define EPS_  1e-7f
#define INV_SQRT_D 0.08838834764831845f

// ---------------- PTX helpers (plain sm_80+ features only) ----------------
__device__ __forceinline__ uint32_t smem_u32(const void* p){
    uint32_t a;
    asm("{ .reg .u64 t; cvta.to.shared.u64 t, %1; cvt.u32.u64 %0, t; }" : "=r"(a) : "l"(p));
    return a;
}
#define CPA(sa, gp) \
    asm volatile("cp.async.cg.shared.global [%0], [%1], 16;" \
        :: "r"(sa), "l"(__cvta_generic_to_global((const void*)(gp))) : "memory")
#define CP_COMMIT() asm volatile("cp.async.commit_group;" ::: "memory")
#define CP_WAIT1()  asm volatile("cp.async.wait_group 1;" ::: "memory")
#define CP_WAIT0()  asm volatile("cp.async.wait_group 0;" ::: "memory")

#define LDSM4(r, addr) \
    asm volatile("ldmatrix.sync.aligned.m8n8.x4.shared.b16 {%0,%1,%2,%3}, [%4];" \
        : "=r"((r)[0]), "=r"((r)[1]), "=r"((r)[2]), "=r"((r)[3]) : "r"(addr))

#define MMA_B16(c, a0,a1,a2,a3, b0,b1) \
    asm volatile("mma.sync.aligned.m16n8k16.row.col.f32.bf16.bf16.f32 " \
        "{%0,%1,%2,%3}, {%4,%5,%6,%7}, {%8,%9}, {%0,%1,%2,%3};" \
        : "+f"((c)[0]), "+f"((c)[1]), "+f"((c)[2]), "+f"((c)[3]) \
        : "r"(a0), "r"(a1), "r"(a2), "r"(a3), "r"(b0), "r"(b1))

__device__ __forceinline__ uint32_t pack_bf2(float a, float b){
    __nv_bfloat162 t = __floats2bfloat162_rn(a, b);
    return *(uint32_t*)&t;
}

// ---------------- scratch ----------------
__device__ float          g_cur [(size_t)M_ * HID_];
__device__ __nv_bfloat16  g_curh[(size_t)M_ * HID_];
__device__ __nv_bfloat16  g_curl[(size_t)M_ * HID_];
__device__ __nv_bfloat16  g_Wqh [(size_t)3 * HID_ * HID_];   // W_qkv^T bf16 [3072,1024]
__device__ __nv_bfloat16  g_Wql [(size_t)3 * HID_ * HID_];
__device__ __nv_bfloat16  g_Woh [(size_t)HID_ * HID_];       // W_out^T hi
__device__ __nv_bfloat16  g_Wol [(size_t)HID_ * HID_];       // W_out^T lo
__device__ __nv_bfloat16  g_Qb  [(size_t)BH_ * S_ * HD_];    // expmapped q * inv_sqrt_d
__device__ __nv_bfloat16  g_Kb  [(size_t)BH_ * S_ * HD_];    // expmapped k
__device__ __nv_bfloat16  g_Vt  [(size_t)BH_ * HD_ * S_];    // V^T [z, d, s]
__device__ float          g_O   [(size_t)M_ * HID_];

// ==================================================================
// MMA core (validated R7): acc += A[128,K] @ B[128,K]^T
// ==================================================================
template<int NT>
__device__ __forceinline__ void mma_core(
    float (&acc)[4][4][4],
    const __nv_bfloat16* __restrict__ Ah, const __nv_bfloat16* __restrict__ Al,
    const __nv_bfloat16* __restrict__ Bh, const __nv_bfloat16* __restrict__ Bl,
    int ldA, int ldB, int K, char* smem)
{
    constexpr int TILE = 128 * 80;
    constexpr int NS   = (NT == 3) ? 4 : 2;
    constexpr int STG  = NS * TILE;
    const int tid  = threadIdx.x;
    const int lane = tid & 31, warp = tid >> 5;
    const int wm = (warp >> 2) * 64;
    const int wn = (warp & 3) * 32;
    const uint32_t sb = smem_u32(smem);

    auto issue = [&](int buf, int k0) {
        #pragma unroll
        for (int i = 0; i < 2; i++) {
            int q = tid + i * 256;
            int r = q >> 2, c = q & 3;
            uint32_t sa = sb + buf * STG + r * 80 + c * 16;
            CPA(sa,                              Ah + (size_t)r * ldA + k0 + c * 8);
            CPA(sa + (NT == 3 ? 2 : 1) * TILE,   Bh + (size_t)r * ldB + k0 + c * 8);
            if (NT == 3) {
                CPA(sa + TILE,                   Al + (size_t)r * ldA + k0 + c * 8);
                CPA(sa + 3 * TILE,               Bl + (size_t)r * ldB + k0 + c * 8);
            }
        }
        CP_COMMIT();
    };

    issue(0, 0);
    const int T = K / 32;
    for (int kt = 0; kt < T; kt++) {
        const int buf = kt & 1;
        if (kt + 1 < T) { issue(buf ^ 1, (kt + 1) * 32); CP_WAIT1(); }
        else            { CP_WAIT0(); }
        __syncthreads();
        const uint32_t ab = sb + buf * STG;
        const uint32_t bb = ab + (NT == 3 ? 2 : 1) * TILE;
        #pragma unroll
        for (int kk = 0; kk < 2; kk++) {
            const uint32_t roff = (uint32_t)(lane & 15) * 80 + (2 * kk + (lane >> 4)) * 16;
            uint32_t bh[8], bl[8];
            LDSM4(bh,     bb + (uint32_t)wn * 80 + roff);
            LDSM4(bh + 4, bb + (uint32_t)(wn + 16) * 80 + roff);
            if (NT == 3) {
                LDSM4(bl,     bb + TILE + (uint32_t)wn * 80 + roff);
                LDSM4(bl + 4, bb + TILE + (uint32_t)(wn + 16) * 80 + roff);
            }
            #pragma unroll
            for (int mi = 0; mi < 4; mi++) {
                uint32_t ah[4], al[4];
                const uint32_t abase = ab + (uint32_t)(wm + mi * 16) * 80 + roff;
                LDSM4(ah, abase);
                if (NT == 3) LDSM4(al, abase + TILE);
                #pragma unroll
                for (int ni = 0; ni < 4; ni++) {
                    const int p = (ni >> 1) * 4, s = ni & 1;
                    uint32_t b0 = bh[p + s], b1 = bh[p + 2 + s];
                    MMA_B16(acc[mi][ni], ah[0], ah[1], ah[2], ah[3], b0, b1);
                    if (NT == 3) {
                        uint32_t d0 = bl[p + s], d1 = bl[p + 2 + s];
                        MMA_B16(acc[mi][ni], ah[0], ah[1], ah[2], ah[3], d0, d1);
                        MMA_B16(acc[mi][ni], al[0], al[1], al[2], al[3], b0, b1);
                    }
                }
            }
        }
        __syncthreads();
    }
}

#define ACC_ZERO(acc) \
    _Pragma("unroll") for (int _i = 0; _i < 4; _i++) \
    _Pragma("unroll") for (int _j = 0; _j < 4; _j++) \
    _Pragma("unroll") for (int _k = 0; _k < 4; _k++) (acc)[_i][_j][_k] = 0.f;

// ==================================================================
// Fused QKV GEMM: one CTA column tile == one head.
// part 0/1 (q/k): expmap0 epilogue (+1/sqrt(d) on q) -> bf16 [z,s,d]
// part 2 (v): transpose epilogue -> bf16 Vt [z,d,s]
// grid (24, 64)
// ==================================================================
__global__ __launch_bounds__(256)
void gemm_qkv_kernel(const __nv_bfloat16* __restrict__ A,
                     const __nv_bfloat16* __restrict__ Bw,
                     const float* __restrict__ bias)
{
    extern __shared__ char smem[];
    const int bx = blockIdx.x;
    const int part = bx >> 3, h = bx & 7;
    const int brow = blockIdx.y * 128;
    const int b = blockIdx.y >> 3, s0 = (blockIdx.y & 7) * 128;
    const int z = b * H_ + h;

    float acc[4][4][4]; ACC_ZERO(acc);
    mma_core<1>(acc, A + (size_t)brow * HID_, nullptr,
                Bw + (size_t)(bx * 128) * HID_, nullptr, HID_, HID_, HID_, smem);

    const int tid = threadIdx.x;
    const int lane = tid & 31, warp = tid >> 5;
    const int wm = (warp >> 2) * 64, wn = (warp & 3) * 32;

    // add bias
    #pragma unroll
    for (int mi = 0; mi < 4; mi++)
        #pragma unroll
        for (int ni = 0; ni < 4; ni++) {
            int gc = bx * 128 + wn + ni * 8 + (lane & 3) * 2;
            acc[mi][ni][0] += bias[gc];     acc[mi][ni][1] += bias[gc + 1];
            acc[mi][ni][2] += bias[gc];     acc[mi][ni][3] += bias[gc + 1];
        }

    __nv_bfloat16* stb = (__nv_bfloat16*)smem;       // 128 x 136 bf16 staging
    float* red = (float*)(smem + 34816);             // [128][4]
    float* scs = (float*)(smem + 36864);             // [128]

    if (part < 2) {
        // per-row sum of squares -> cross-warp reduce -> tanh(n)/n
        #pragma unroll
        for (int mi = 0; mi < 4; mi++) {
            int ra = wm + mi * 16 + (lane >> 2), rb = ra + 8;
            float ssa = 0.f, ssb = 0.f;
            #pragma unroll
            for (int ni = 0; ni < 4; ni++) {
                ssa += acc[mi][ni][0]*acc[mi][ni][0] + acc[mi][ni][1]*acc[mi][ni][1];
                ssb += acc[mi][ni][2]*acc[mi][ni][2] + acc[mi][ni][3]*acc[mi][ni][3];
            }
            ssa += __shfl_xor_sync(0xffffffffu, ssa, 1);
            ssa += __shfl_xor_sync(0xffffffffu, ssa, 2);
            ssb += __shfl_xor_sync(0xffffffffu, ssb, 1);
            ssb += __shfl_xor_sync(0xffffffffu, ssb, 2);
            if ((lane & 3) == 0) {
                red[ra * 4 + (warp & 3)] = ssa;
                red[rb * 4 + (warp & 3)] = ssb;
            }
        }
        __syncthreads();
        if (tid < 128) {
            float t = red[tid*4] + red[tid*4+1] + red[tid*4+2] + red[tid*4+3];
            float n = fmaxf(sqrtf(t), EPS_);
            float sc = tanhf(n) / n;
            if (part == 0) sc *= INV_SQRT_D;
            scs[tid] = sc;
        }
        __syncthreads();
        #pragma unroll
        for (int mi = 0; mi < 4; mi++) {
            int ra = wm + mi * 16 + (lane >> 2), rb = ra + 8;
            float sa = scs[ra], sb2 = scs[rb];
            #pragma unroll
            for (int ni = 0; ni < 4; ni++) {
                int c = wn + ni * 8 + (lane & 3) * 2;
                *(__nv_bfloat162*)&stb[ra * 136 + c] =
                    __floats2bfloat162_rn(acc[mi][ni][0]*sa, acc[mi][ni][1]*sa);
                *(__nv_bfloat162*)&stb[rb * 136 + c] =
                    __floats2bfloat162_rn(acc[mi][ni][2]*sb2, acc[mi][ni][3]*sb2);
            }
        }
        __syncthreads();
        __nv_bfloat16* dst = (part ? g_Kb : g_Qb) + ((size_t)z * S_ + s0) * HD_;
        #pragma unroll
        for (int k = 0; k < 16; k++) {
            int ch = tid + k * 256;
            int outer = ch >> 5, in4 = (ch & 31) * 4;
            *(uint2*)(dst + (size_t)outer * HD_ + in4) = *(uint2*)&stb[outer * 136 + in4];
        }
    } else {
        // V: transposed staging (outer = d, inner = s)
        #pragma unroll
        for (int mi = 0; mi < 4; mi++) {
            int ra = wm + mi * 16 + (lane >> 2), rb = ra + 8;
            #pragma unroll
            for (int ni = 0; ni < 4; ni++) {
                int c = wn + ni * 8 + (lane & 3) * 2;
                stb[c * 136 + ra]       = __float2bfloat16(acc[mi][ni][0]);
                stb[(c + 1) * 136 + ra] = __float2bfloat16(acc[mi][ni][1]);
                stb[c * 136 + rb]       = __float2bfloat16(acc[mi][ni][2]);
                stb[(c + 1) * 136 + rb] = __float2bfloat16(acc[mi][ni][3]);
            }
        }
        __syncthreads();
        __nv_bfloat16* dst = g_Vt + (size_t)z * HD_ * S_ + s0;
        #pragma unroll
        for (int k = 0; k < 16; k++) {
            int ch = tid + k * 256;
            int outer = ch >> 5, in4 = (ch & 31) * 4;
            *(uint2*)(dst + (size_t)outer * S_ + in4) = *(uint2*)&stb[outer * 136 + in4];
        }
    }
}

// ==================================================================
// Flash attention: CTA = 128 q-rows of one head; loop over 8 K/V blocks.
// No max subtraction needed (|score| <= 1/sqrt(128), proven bound).
// grid (8, 64), 256 threads, smem = 5*34816 = 174080 B.
// ==================================================================
__global__ __launch_bounds__(256, 1)
void flash_kernel()
{
    extern __shared__ char smem[];
    const int qb = blockIdx.x, z = blockIdx.y;
    const int b = z >> 3, h = z & 7;
    const int tid = threadIdx.x, lane = tid & 31, warp = tid >> 5;
    const uint32_t sb = smem_u32(smem);
    const int STR = 272;                       // 128 cols bf16 + 16B pad
    const uint32_t Qs = sb;
    const uint32_t Ks[2] = { sb + 34816u, sb + 3u * 34816u };
    const uint32_t Vs[2] = { sb + 2u * 34816u, sb + 4u * 34816u };

    const __nv_bfloat16* Qg = g_Qb + ((size_t)z * S_ + qb * 128) * HD_;
    const __nv_bfloat16* Kg = g_Kb + (size_t)z * S_ * HD_;
    const __nv_bfloat16* Vg = g_Vt + (size_t)z * HD_ * S_;

    auto issueKV = [&](int buf, int kb) {
        #pragma unroll
        for (int i = 0; i < 8; i++) {
            int ch = tid + i * 256;
            int r = ch >> 4, c = ch & 15;
            CPA(Ks[buf] + r * STR + c * 16, Kg + (size_t)(kb * 128 + r) * HD_ + c * 8);
            CPA(Vs[buf] + r * STR + c * 16, Vg + (size_t)r * S_ + kb * 128 + c * 8);
        }
        CP_COMMIT();
    };

    // group0: Q + KV0 ; group1: KV1
    #pragma unroll
    for (int i = 0; i < 8; i++) {
        int ch = tid + i * 256;
        int r = ch >> 4, c = ch & 15;
        CPA(Qs + r * STR + c * 16, Qg + (size_t)r * HD_ + c * 8);
    }
    {
        #pragma unroll
        for (int i = 0; i < 8; i++) {
            int ch = tid + i * 256;
            int r = ch >> 4, c = ch & 15;
            CPA(Ks[0] + r * STR + c * 16, Kg + (size_t)r * HD_ + c * 8);
            CPA(Vs[0] + r * STR + c * 16, Vg + (size_t)r * S_ + c * 8);
        }
        CP_COMMIT();
    }
    issueKV(1, 1);

    float acc_o[16][4];
    #pragma unroll
    for (int i = 0; i < 16; i++)
        #pragma unroll
        for (int j = 0; j < 4; j++) acc_o[i][j] = 0.f;
    float l0 = 0.f, l1 = 0.f;

    for (int kb = 0; kb < 8; kb++) {
        if (kb < 7) CP_WAIT1(); else CP_WAIT0();
        __syncthreads();
        const int buf = kb & 1;
        const uint32_t Kb = Ks[buf], Vb = Vs[buf];

        // S = Q @ K^T  (warp: 16 rows x 128 cols)
        float acc_s[16][4];
        #pragma unroll
        for (int i = 0; i < 16; i++)
            #pragma unroll
            for (int j = 0; j < 4; j++) acc_s[i][j] = 0.f;

        #pragma unroll
        for (int ks = 0; ks < 8; ks++) {
            const uint32_t roff = (uint32_t)(lane & 15) * STR + (2 * ks + (lane >> 4)) * 16;
            uint32_t aq[4];
            LDSM4(aq, Qs + (uint32_t)(warp * 16) * STR + roff);
            #pragma unroll
            for (int nt = 0; nt < 8; nt++) {
                uint32_t bh[4];
                LDSM4(bh, Kb + (uint32_t)(nt * 16) * STR + roff);
                MMA_B16(acc_s[2 * nt],     aq[0], aq[1], aq[2], aq[3], bh[0], bh[2]);
                MMA_B16(acc_s[2 * nt + 1], aq[0], aq[1], aq[2], aq[3], bh[1], bh[3]);
            }
        }

        // P = exp(S) (no max needed), accumulate l, repack C->A fragments
        uint32_t Af[8][4];
        #pragma unroll
        for (int nt2 = 0; nt2 < 16; nt2++) {
            float e0 = __expf(acc_s[nt2][0]);
            float e1 = __expf(acc_s[nt2][1]);
            float e2 = __expf(acc_s[nt2][2]);
            float e3 = __expf(acc_s[nt2][3]);
            l0 += e0 + e1;
            l1 += e2 + e3;
            int kt = nt2 >> 1, hf = (nt2 & 1) * 2;
            Af[kt][hf]     = pack_bf2(e0, e1);
            Af[kt][hf + 1] = pack_bf2(e2, e3);
        }

        // O += P @ V   (k = s-block 128, n = d 128)
        #pragma unroll
        for (int kt = 0; kt < 8; kt++) {
            const uint32_t roff = (uint32_t)(lane & 15) * STR + (2 * kt + (lane >> 4)) * 16;
            #pragma unroll
            for (int nt = 0; nt < 8; nt++) {
                uint32_t bv[4];
                LDSM4(bv, Vb + (uint32_t)(nt * 16) * STR + roff);
                MMA_B16(acc_o[2 * nt],     Af[kt][0], Af[kt][1], Af[kt][2], Af[kt][3], bv[0], bv[2]);
                MMA_B16(acc_o[2 * nt + 1], Af[kt][0], Af[kt][1], Af[kt][2], Af[kt][3], bv[1], bv[3]);
            }
        }
        __syncthreads();
        if (kb + 2 < 8) issueKV(buf, kb + 2);
    }

    // normalize and write O
    l0 += __shfl_xor_sync(0xffffffffu, l0, 1);
    l0 += __shfl_xor_sync(0xffffffffu, l0, 2);
    l1 += __shfl_xor_sync(0xffffffffu, l1, 1);
    l1 += __shfl_xor_sync(0xffffffffu, l1, 2);
    float i0 = 1.f / l0, i1 = 1.f / l1;
    const int r  = qb * 128 + warp * 16 + (lane >> 2);
    #pragma unroll
    for (int nt2 = 0; nt2 < 16; nt2++) {
        int c = nt2 * 8 + (lane & 3) * 2;
        *(float2*)&g_O[((size_t)(b * S_ + r) * HID_) + h * HD_ + c] =
            make_float2(acc_o[nt2][0] * i0, acc_o[nt2][1] * i0);
        *(float2*)&g_O[((size_t)(b * S_ + r + 8) * HID_) + h * HD_ + c] =
            make_float2(acc_o[nt2][2] * i1, acc_o[nt2][3] * i1);
    }
}

// ---- out-proj GEMM (hi/lo split): C = (Ah+Al)@(Bh+Bl)^T + bias ----
__global__ __launch_bounds__(256)
void gemm3_kernel(const __nv_bfloat16* __restrict__ Ah, const __nv_bfloat16* __restrict__ Al,
                  const __nv_bfloat16* __restrict__ Bh, const __nv_bfloat16* __restrict__ Bl,
                  const float* __restrict__ bias, float* __restrict__ C, int N, int K)
{
    extern __shared__ char smem[];
    const int brow = blockIdx.y * 128, bcol = blockIdx.x * 128;
    float acc[4][4][4]; ACC_ZERO(acc);
    mma_core<3>(acc, Ah + (size_t)brow * K, Al + (size_t)brow * K,
                     Bh + (size_t)bcol * K, Bl + (size_t)bcol * K, K, K, K, smem);
    const int lane = threadIdx.x & 31, warp = threadIdx.x >> 5;
    const int wm = (warp >> 2) * 64, wn = (warp & 3) * 32;
    #pragma unroll
    for (int mi = 0; mi < 4; mi++)
        #pragma unroll
        for (int ni = 0; ni < 4; ni++) {
            int r = brow + wm + mi * 16 + (lane >> 2);
            int c = bcol + wn + ni * 8 + (lane & 3) * 2;
            float bx = bias[c], by = bias[c + 1];
            *(float2*)&C[(size_t)r * N + c]       = make_float2(acc[mi][ni][0] + bx, acc[mi][ni][1] + by);
            *(float2*)&C[(size_t)(r + 8) * N + c] = make_float2(acc[mi][ni][2] + bx, acc[mi][ni][3] + by);
        }
}

// ---------------- small kernels ----------------
__device__ __forceinline__ void split_store(float v, __nv_bfloat16* h, __nv_bfloat16* l, size_t i){
    __nv_bfloat16 hi = __float2bfloat16(v);
    h[i] = hi;
    l[i] = __float2bfloat16(v - __bfloat162float(hi));
}

__global__ void copy_x_kernel(const float* __restrict__ x){
    size_t i = (size_t)blockIdx.x * blockDim.x + threadIdx.x;
    float4 v = ((const float4*)x)[i];
    ((float4*)g_cur)[i] = v;
    size_t e = i * 4;
    split_store(v.x, g_curh, g_curl, e + 0);
    split_store(v.y, g_curh, g_curl, e + 1);
    split_store(v.z, g_curh, g_curl, e + 2);
    split_store(v.w, g_curh, g_curl, e + 3);
}

__global__ void wt_kernel(const float* __restrict__ src,
                          __nv_bfloat16* __restrict__ dh, __nv_bfloat16* __restrict__ dl,
                          int K, int N)
{
    __shared__ float t[32][33];
    const int n0 = blockIdx.x * 32, k0 = blockIdx.y * 32;
    const int tx = threadIdx.x, ty = threadIdx.y;
    for (int i = ty; i < 32; i += 8)
        t[i][tx] = src[(size_t)(k0 + i) * N + n0 + tx];
    __syncthreads();
    for (int i = ty; i < 32; i += 8)
        split_store(t[tx][i], dh, dl, (size_t)(n0 + i) * K + k0 + tx);
}

// cur += (O @ W_pinv + b_pinv) @ Wa + ba ; refresh hi/lo
__global__ void update_kernel(const float* __restrict__ W_pinv, const float* __restrict__ b_pinv,
                              const float* __restrict__ Wa, const float* __restrict__ ba)
{
    const int row = blockIdx.x, tid = threadIdx.x;
    const int warp = tid >> 5, lane = tid & 31;
    const float* orow = g_O + (size_t)row * HID_;
    __shared__ float m[MD_];
    float acc = 0.f;
    for (int i = lane; i < HID_; i += 32)
        acc += orow[i] * W_pinv[i * MD_ + warp];
    #pragma unroll
    for (int o = 16; o > 0; o >>= 1) acc += __shfl_xor_sync(0xffffffffu, acc, o);
    if (lane == 0) m[warp] = acc + b_pinv[warp];
    __syncthreads();
    float mv[MD_];
    #pragma unroll
    for (int j = 0; j < MD_; j++) mv[j] = m[j];
    #pragma unroll
    for (int t = 0; t < HID_ / 256; t++) {
        int col = tid + t * 256;
        float u = ba[col];
        #pragma unroll
        for (int j = 0; j < MD_; j++) u += mv[j] * Wa[j * HID_ + col];
        size_t idx = (size_t)row * HID_ + col;
        float nc = g_cur[idx] + u;
        g_cur[idx] = nc;
        split_store(nc, g_curh, g_curl, idx);
    }
}

// ---------------- launcher ----------------
extern "C" void kernel_launch(void* const* d_in, const int* in_sizes, int n_in,
                              void* d_out, int out_size)
{
    const float* x      = (const float*)d_in[0];
    const float* W_qkv  = (const float*)d_in[1];
    const float* b_qkv  = (const float*)d_in[2];
    const float* W_pinv = (const float*)d_in[3];
    const float* b_pinv = (const float*)d_in[4];
    const float* W_attn = (const float*)d_in[5];
    const float* b_attn = (const float*)d_in[6];
    const float* W_out  = (const float*)d_in[7];
    const float* b_out  = (const float*)d_in[8];
    float* out = (float*)d_out;

    const int SM1 = 2 * 2 * 128 * 80;   // 40960 (gemm_qkv; also covers staging 37376)
    const int SM3 = 2 * 4 * 128 * 80;   // 81920
    const int SMF = 5 * 34816;          // 174080 (flash)
    cudaFuncSetAttribute(gemm_qkv_kernel, cudaFuncAttributeMaxDynamicSharedMemorySize, SM1);
    cudaFuncSetAttribute(gemm3_kernel,    cudaFuncAttributeMaxDynamicSharedMemorySize, SM3);
    cudaFuncSetAttribute(flash_kernel,    cudaFuncAttributeMaxDynamicSharedMemorySize, SMF);

    __nv_bfloat16 *curh = nullptr, *curl = nullptr, *wqh = nullptr, *wql = nullptr,
                  *woh = nullptr, *wol = nullptr;
    cudaGetSymbolAddress((void**)&curh, g_curh);
    cudaGetSymbolAddress((void**)&curl, g_curl);
    cudaGetSymbolAddress((void**)&wqh,  g_Wqh);
    cudaGetSymbolAddress((void**)&wql,  g_Wql);
    cudaGetSymbolAddress((void**)&woh,  g_Woh);
    cudaGetSymbolAddress((void**)&wol,  g_Wol);

    copy_x_kernel<<<(M_ * HID_) / 4 / 256, 256>>>(x);
    wt_kernel<<<dim3(3 * HID_ / 32, HID_ / 32), dim3(32, 8)>>>(W_qkv, wqh, wql, HID_, 3 * HID_);
    wt_kernel<<<dim3(HID_ / 32, HID_ / 32), dim3(32, 8)>>>(W_out, woh, wol, HID_, HID_);

    for (int l = 0; l < L_; ++l) {
        // qkv GEMM fused with expmap/split/transpose epilogues
        gemm_qkv_kernel<<<dim3(24, 64), 256, SM1>>>(curh, wqh, b_qkv);
        // fused scores+softmax+PV
        flash_kernel<<<dim3(8, BH_), 256, SMF>>>();
        // manifold update
        update_kernel<<<M_, 256>>>(W_pinv, b_pinv,
                                   W_attn + (size_t)l * MD_ * HID_,
                                   b_attn + (size_t)l * HID_);
    }

    // out = cur @ W_out + b_out (hi/lo split)
    gemm3_kernel<<<dim3(HID_ / 128, M_ / 128), 256, SM3>>>(
        curh, curl, woh, wol, b_out, out, HID_, HID_);
}

// round 11
// speedup vs baseline: 5.4354x; 1.0059x over previous
#include <cuda_runtime.h>
#include <cuda_bf16.h>
#include <cstdint>
#include <math.h>

#define B_    8
#define S_    1024
#define HID_  1024
#define H_    8
#define HD_   128
#define MD_   8
#define L_    3
#define M_    (B_*S_)
#define BH_   (B_*H_)
#define EPS_  1e-7f
#define INV_SQRT_D 0.08838834764831845f

// ---------------- PTX helpers (plain sm_80+ features only) ----------------
__device__ __forceinline__ uint32_t smem_u32(const void* p){
    uint32_t a;
    asm("{ .reg .u64 t; cvta.to.shared.u64 t, %1; cvt.u32.u64 %0, t; }" : "=r"(a) : "l"(p));
    return a;
}
#define CPA(sa, gp) \
    asm volatile("cp.async.cg.shared.global [%0], [%1], 16;" \
        :: "r"(sa), "l"(__cvta_generic_to_global((const void*)(gp))) : "memory")
#define CP_COMMIT() asm volatile("cp.async.commit_group;" ::: "memory")
#define CP_WAIT2()  asm volatile("cp.async.wait_group 2;" ::: "memory")
#define CP_WAIT1()  asm volatile("cp.async.wait_group 1;" ::: "memory")
#define CP_WAIT0()  asm volatile("cp.async.wait_group 0;" ::: "memory")

#define LDSM4(r, addr) \
    asm volatile("ldmatrix.sync.aligned.m8n8.x4.shared.b16 {%0,%1,%2,%3}, [%4];" \
        : "=r"((r)[0]), "=r"((r)[1]), "=r"((r)[2]), "=r"((r)[3]) : "r"(addr))

#define MMA_B16(c, a0,a1,a2,a3, b0,b1) \
    asm volatile("mma.sync.aligned.m16n8k16.row.col.f32.bf16.bf16.f32 " \
        "{%0,%1,%2,%3}, {%4,%5,%6,%7}, {%8,%9}, {%0,%1,%2,%3};" \
        : "+f"((c)[0]), "+f"((c)[1]), "+f"((c)[2]), "+f"((c)[3]) \
        : "r"(a0), "r"(a1), "r"(a2), "r"(a3), "r"(b0), "r"(b1))

__device__ __forceinline__ uint32_t pack_bf2(float a, float b){
    __nv_bfloat162 t = __floats2bfloat162_rn(a, b);
    return *(uint32_t*)&t;
}

// ---------------- scratch ----------------
__device__ float          g_cur [(size_t)M_ * HID_];
__device__ __nv_bfloat16  g_curh[(size_t)M_ * HID_];
__device__ __nv_bfloat16  g_curl[(size_t)M_ * HID_];
__device__ __nv_bfloat16  g_Wqh [(size_t)3 * HID_ * HID_];   // W_qkv^T bf16 [3072,1024]
__device__ __nv_bfloat16  g_Wql [(size_t)3 * HID_ * HID_];
__device__ __nv_bfloat16  g_Woh [(size_t)HID_ * HID_];       // W_out^T hi
__device__ __nv_bfloat16  g_Wol [(size_t)HID_ * HID_];       // W_out^T lo
__device__ __nv_bfloat16  g_Qb  [(size_t)BH_ * S_ * HD_];    // expmapped q * inv_sqrt_d
__device__ __nv_bfloat16  g_Kb  [(size_t)BH_ * S_ * HD_];    // expmapped k
__device__ __nv_bfloat16  g_Vt  [(size_t)BH_ * HD_ * S_];    // V^T [z, d, s]
__device__ float          g_O   [(size_t)M_ * HID_];

// ==================================================================
// MMA core: acc += A[128,K] @ B[128,K]^T  (bf16 in, fp32 acc)
// STAGES-deep cp.async pipeline (3 for NT=1, 2 for NT=3).
// ==================================================================
template<int NT, int STAGES>
__device__ __forceinline__ void mma_core(
    float (&acc)[4][4][4],
    const __nv_bfloat16* __restrict__ Ah, const __nv_bfloat16* __restrict__ Al,
    const __nv_bfloat16* __restrict__ Bh, const __nv_bfloat16* __restrict__ Bl,
    int ldA, int ldB, int K, char* smem)
{
    constexpr int TILE = 128 * 80;
    constexpr int NS   = (NT == 3) ? 4 : 2;
    constexpr int STG  = NS * TILE;
    const int tid  = threadIdx.x;
    const int lane = tid & 31, warp = tid >> 5;
    const int wm = (warp >> 2) * 64;
    const int wn = (warp & 3) * 32;
    const uint32_t sb = smem_u32(smem);

    auto issue = [&](int stage, int k0) {
        #pragma unroll
        for (int i = 0; i < 2; i++) {
            int q = tid + i * 256;
            int r = q >> 2, c = q & 3;
            uint32_t sa = sb + stage * STG + r * 80 + c * 16;
            CPA(sa,                              Ah + (size_t)r * ldA + k0 + c * 8);
            CPA(sa + (NT == 3 ? 2 : 1) * TILE,   Bh + (size_t)r * ldB + k0 + c * 8);
            if (NT == 3) {
                CPA(sa + TILE,                   Al + (size_t)r * ldA + k0 + c * 8);
                CPA(sa + 3 * TILE,               Bl + (size_t)r * ldB + k0 + c * 8);
            }
        }
        CP_COMMIT();
    };

    #pragma unroll
    for (int s = 0; s < STAGES - 1; s++) issue(s, s * 32);

    const int T = K / 32;
    for (int kt = 0; kt < T; kt++) {
        int rem;
        if (kt + STAGES - 1 < T) {
            issue((kt + STAGES - 1) % STAGES, (kt + STAGES - 1) * 32);
            rem = STAGES - 1;
        } else {
            rem = T - 1 - kt;
        }
        if (rem >= 2) CP_WAIT2(); else if (rem == 1) CP_WAIT1(); else CP_WAIT0();
        __syncthreads();
        const uint32_t ab = sb + (kt % STAGES) * STG;
        const uint32_t bb = ab + (NT == 3 ? 2 : 1) * TILE;
        #pragma unroll
        for (int kk = 0; kk < 2; kk++) {
            const uint32_t roff = (uint32_t)(lane & 15) * 80 + (2 * kk + (lane >> 4)) * 16;
            uint32_t bh[8], bl[8];
            LDSM4(bh,     bb + (uint32_t)wn * 80 + roff);
            LDSM4(bh + 4, bb + (uint32_t)(wn + 16) * 80 + roff);
            if (NT == 3) {
                LDSM4(bl,     bb + TILE + (uint32_t)wn * 80 + roff);
                LDSM4(bl + 4, bb + TILE + (uint32_t)(wn + 16) * 80 + roff);
            }
            #pragma unroll
            for (int mi = 0; mi < 4; mi++) {
                uint32_t ah[4], al[4];
                const uint32_t abase = ab + (uint32_t)(wm + mi * 16) * 80 + roff;
                LDSM4(ah, abase);
                if (NT == 3) LDSM4(al, abase + TILE);
                #pragma unroll
                for (int ni = 0; ni < 4; ni++) {
                    const int p = (ni >> 1) * 4, s = ni & 1;
                    uint32_t b0 = bh[p + s], b1 = bh[p + 2 + s];
                    MMA_B16(acc[mi][ni], ah[0], ah[1], ah[2], ah[3], b0, b1);
                    if (NT == 3) {
                        uint32_t d0 = bl[p + s], d1 = bl[p + 2 + s];
                        MMA_B16(acc[mi][ni], ah[0], ah[1], ah[2], ah[3], d0, d1);
                        MMA_B16(acc[mi][ni], al[0], al[1], al[2], al[3], b0, b1);
                    }
                }
            }
        }
        __syncthreads();
    }
}

#define ACC_ZERO(acc) \
    _Pragma("unroll") for (int _i = 0; _i < 4; _i++) \
    _Pragma("unroll") for (int _j = 0; _j < 4; _j++) \
    _Pragma("unroll") for (int _k = 0; _k < 4; _k++) (acc)[_i][_j][_k] = 0.f;

// ==================================================================
// Fused QKV GEMM: one CTA column tile == one head.
// part 0/1 (q/k): expmap0 epilogue (+1/sqrt(d) on q) -> bf16 [z,s,d]
// part 2 (v): transpose epilogue -> bf16 Vt [z,d,s]
// grid (24, 64), smem = 3*2*10240 = 61440
// ==================================================================
__global__ __launch_bounds__(256)
void gemm_qkv_kernel(const __nv_bfloat16* __restrict__ A,
                     const __nv_bfloat16* __restrict__ Bw,
                     const float* __restrict__ bias)
{
    extern __shared__ char smem[];
    const int bx = blockIdx.x;
    const int part = bx >> 3, h = bx & 7;
    const int brow = blockIdx.y * 128;
    const int b = blockIdx.y >> 3, s0 = (blockIdx.y & 7) * 128;
    const int z = b * H_ + h;

    float acc[4][4][4]; ACC_ZERO(acc);
    mma_core<1, 3>(acc, A + (size_t)brow * HID_, nullptr,
                   Bw + (size_t)(bx * 128) * HID_, nullptr, HID_, HID_, HID_, smem);

    const int tid = threadIdx.x;
    const int lane = tid & 31, warp = tid >> 5;
    const int wm = (warp >> 2) * 64, wn = (warp & 3) * 32;

    // add bias
    #pragma unroll
    for (int mi = 0; mi < 4; mi++)
        #pragma unroll
        for (int ni = 0; ni < 4; ni++) {
            int gc = bx * 128 + wn + ni * 8 + (lane & 3) * 2;
            acc[mi][ni][0] += bias[gc];     acc[mi][ni][1] += bias[gc + 1];
            acc[mi][ni][2] += bias[gc];     acc[mi][ni][3] += bias[gc + 1];
        }

    __nv_bfloat16* stb = (__nv_bfloat16*)smem;       // 128 x 136 bf16 staging
    float* red = (float*)(smem + 34816);             // [128][4]
    float* scs = (float*)(smem + 36864);             // [128]

    if (part < 2) {
        // per-row sum of squares -> cross-warp reduce -> tanh(n)/n
        #pragma unroll
        for (int mi = 0; mi < 4; mi++) {
            int ra = wm + mi * 16 + (lane >> 2), rb = ra + 8;
            float ssa = 0.f, ssb = 0.f;
            #pragma unroll
            for (int ni = 0; ni < 4; ni++) {
                ssa += acc[mi][ni][0]*acc[mi][ni][0] + acc[mi][ni][1]*acc[mi][ni][1];
                ssb += acc[mi][ni][2]*acc[mi][ni][2] + acc[mi][ni][3]*acc[mi][ni][3];
            }
            ssa += __shfl_xor_sync(0xffffffffu, ssa, 1);
            ssa += __shfl_xor_sync(0xffffffffu, ssa, 2);
            ssb += __shfl_xor_sync(0xffffffffu, ssb, 1);
            ssb += __shfl_xor_sync(0xffffffffu, ssb, 2);
            if ((lane & 3) == 0) {
                red[ra * 4 + (warp & 3)] = ssa;
                red[rb * 4 + (warp & 3)] = ssb;
            }
        }
        __syncthreads();
        if (tid < 128) {
            float t = red[tid*4] + red[tid*4+1] + red[tid*4+2] + red[tid*4+3];
            float n = fmaxf(sqrtf(t), EPS_);
            float sc = tanhf(n) / n;
            if (part == 0) sc *= INV_SQRT_D;
            scs[tid] = sc;
        }
        __syncthreads();
        #pragma unroll
        for (int mi = 0; mi < 4; mi++) {
            int ra = wm + mi * 16 + (lane >> 2), rb = ra + 8;
            float sa = scs[ra], sb2 = scs[rb];
            #pragma unroll
            for (int ni = 0; ni < 4; ni++) {
                int c = wn + ni * 8 + (lane & 3) * 2;
                *(__nv_bfloat162*)&stb[ra * 136 + c] =
                    __floats2bfloat162_rn(acc[mi][ni][0]*sa, acc[mi][ni][1]*sa);
                *(__nv_bfloat162*)&stb[rb * 136 + c] =
                    __floats2bfloat162_rn(acc[mi][ni][2]*sb2, acc[mi][ni][3]*sb2);
            }
        }
        __syncthreads();
        __nv_bfloat16* dst = (part ? g_Kb : g_Qb) + ((size_t)z * S_ + s0) * HD_;
        #pragma unroll
        for (int k = 0; k < 16; k++) {
            int ch = tid + k * 256;
            int outer = ch >> 5, in4 = (ch & 31) * 4;
            *(uint2*)(dst + (size_t)outer * HD_ + in4) = *(uint2*)&stb[outer * 136 + in4];
        }
    } else {
        // V: transposed staging (outer = d, inner = s)
        #pragma unroll
        for (int mi = 0; mi < 4; mi++) {
            int ra = wm + mi * 16 + (lane >> 2), rb = ra + 8;
            #pragma unroll
            for (int ni = 0; ni < 4; ni++) {
                int c = wn + ni * 8 + (lane & 3) * 2;
                stb[c * 136 + ra]       = __float2bfloat16(acc[mi][ni][0]);
                stb[(c + 1) * 136 + ra] = __float2bfloat16(acc[mi][ni][1]);
                stb[c * 136 + rb]       = __float2bfloat16(acc[mi][ni][2]);
                stb[(c + 1) * 136 + rb] = __float2bfloat16(acc[mi][ni][3]);
            }
        }
        __syncthreads();
        __nv_bfloat16* dst = g_Vt + (size_t)z * HD_ * S_ + s0;
        #pragma unroll
        for (int k = 0; k < 16; k++) {
            int ch = tid + k * 256;
            int outer = ch >> 5, in4 = (ch & 31) * 4;
            *(uint2*)(dst + (size_t)outer * S_ + in4) = *(uint2*)&stb[outer * 136 + in4];
        }
    }
}

// ==================================================================
// Flash attention, KB=64 K-blocks for 2 CTAs/SM.
// CTA = 128 q-rows of one head; 16 K/V blocks of 64.
// No max subtraction needed (|score| <= 1/sqrt(128)).
// grid (8, 64), 256 threads, smem = 34816 + 2*(17408+18432) = 106496 B.
// ==================================================================
#define STRQ 272   // Q/K row: 128 bf16 + 16B pad
#define STRV 144   // V row: 64 bf16 + 16B pad
__global__ __launch_bounds__(256, 2)
void flash_kernel()
{
    extern __shared__ char smem[];
    const int qb = blockIdx.x, z = blockIdx.y;
    const int b = z >> 3, h = z & 7;
    const int tid = threadIdx.x, lane = tid & 31, warp = tid >> 5;
    const uint32_t sb = smem_u32(smem);
    const uint32_t Qs = sb;
    const uint32_t Ks[2] = { sb + 34816u,  sb + 70656u };
    const uint32_t Vs[2] = { sb + 52224u,  sb + 88064u };

    const __nv_bfloat16* Qg = g_Qb + ((size_t)z * S_ + qb * 128) * HD_;
    const __nv_bfloat16* Kg = g_Kb + (size_t)z * S_ * HD_;
    const __nv_bfloat16* Vg = g_Vt + (size_t)z * HD_ * S_;

    auto issueKV = [&](int buf, int kb) {
        #pragma unroll
        for (int i = 0; i < 4; i++) {              // K: 64 rows x 16 chunks
            int ch = tid + i * 256;
            int r = ch >> 4, c = ch & 15;
            CPA(Ks[buf] + r * STRQ + c * 16, Kg + (size_t)(kb * 64 + r) * HD_ + c * 8);
        }
        #pragma unroll
        for (int i = 0; i < 4; i++) {              // V: 128 rows x 8 chunks
            int ch = tid + i * 256;
            int r = ch >> 3, c = ch & 7;
            CPA(Vs[buf] + r * STRV + c * 16, Vg + (size_t)r * S_ + kb * 64 + c * 8);
        }
        CP_COMMIT();
    };

    // group0: Q + KV block 0 ; group1: KV block 1
    #pragma unroll
    for (int i = 0; i < 8; i++) {
        int ch = tid + i * 256;
        int r = ch >> 4, c = ch & 15;
        CPA(Qs + r * STRQ + c * 16, Qg + (size_t)r * HD_ + c * 8);
    }
    issueKV(0, 0);          // commits Q + K0 + V0 as group 0
    issueKV(1, 1);          // group 1

    float acc_o[16][4];
    #pragma unroll
    for (int i = 0; i < 16; i++)
        #pragma unroll
        for (int j = 0; j < 4; j++) acc_o[i][j] = 0.f;
    float l0 = 0.f, l1 = 0.f;

    for (int kb = 0; kb < 16; kb++) {
        if (kb < 15) CP_WAIT1(); else CP_WAIT0();
        __syncthreads();
        const int buf = kb & 1;
        const uint32_t Kb = Ks[buf], Vb = Vs[buf];

        // S = Q @ K^T  (warp: 16 rows x 64 cols)
        float acc_s[8][4];
        #pragma unroll
        for (int i = 0; i < 8; i++)
            #pragma unroll
            for (int j = 0; j < 4; j++) acc_s[i][j] = 0.f;

        #pragma unroll
        for (int ks = 0; ks < 8; ks++) {
            const uint32_t roff = (uint32_t)(lane & 15) * STRQ + (2 * ks + (lane >> 4)) * 16;
            uint32_t aq[4];
            LDSM4(aq, Qs + (uint32_t)(warp * 16) * STRQ + roff);
            #pragma unroll
            for (int nt = 0; nt < 4; nt++) {
                uint32_t bh[4];
                LDSM4(bh, Kb + (uint32_t)(nt * 16) * STRQ + roff);
                MMA_B16(acc_s[2 * nt],     aq[0], aq[1], aq[2], aq[3], bh[0], bh[2]);
                MMA_B16(acc_s[2 * nt + 1], aq[0], aq[1], aq[2], aq[3], bh[1], bh[3]);
            }
        }

        // P = exp(S), accumulate l, repack C->A fragments
        uint32_t Af[4][4];
        #pragma unroll
        for (int nt2 = 0; nt2 < 8; nt2++) {
            float e0 = __expf(acc_s[nt2][0]);
            float e1 = __expf(acc_s[nt2][1]);
            float e2 = __expf(acc_s[nt2][2]);
            float e3 = __expf(acc_s[nt2][3]);
            l0 += e0 + e1;
            l1 += e2 + e3;
            int kt = nt2 >> 1, hf = (nt2 & 1) * 2;
            Af[kt][hf]     = pack_bf2(e0, e1);
            Af[kt][hf + 1] = pack_bf2(e2, e3);
        }

        // O += P @ V   (k = 64 s-positions, n = d 128)
        #pragma unroll
        for (int kt = 0; kt < 4; kt++) {
            const uint32_t roff = (uint32_t)(lane & 15) * STRV + (2 * kt + (lane >> 4)) * 16;
            #pragma unroll
            for (int nt = 0; nt < 8; nt++) {
                uint32_t bv[4];
                LDSM4(bv, Vb + (uint32_t)(nt * 16) * STRV + roff);
                MMA_B16(acc_o[2 * nt],     Af[kt][0], Af[kt][1], Af[kt][2], Af[kt][3], bv[0], bv[2]);
                MMA_B16(acc_o[2 * nt + 1], Af[kt][0], Af[kt][1], Af[kt][2], Af[kt][3], bv[1], bv[3]);
            }
        }
        __syncthreads();
        if (kb + 2 < 16) issueKV(buf, kb + 2);
    }

    // normalize and write O
    l0 += __shfl_xor_sync(0xffffffffu, l0, 1);
    l0 += __shfl_xor_sync(0xffffffffu, l0, 2);
    l1 += __shfl_xor_sync(0xffffffffu, l1, 1);
    l1 += __shfl_xor_sync(0xffffffffu, l1, 2);
    float i0 = 1.f / l0, i1 = 1.f / l1;
    const int r  = qb * 128 + warp * 16 + (lane >> 2);
    #pragma unroll
    for (int nt2 = 0; nt2 < 16; nt2++) {
        int c = nt2 * 8 + (lane & 3) * 2;
        *(float2*)&g_O[((size_t)(b * S_ + r) * HID_) + h * HD_ + c] =
            make_float2(acc_o[nt2][0] * i0, acc_o[nt2][1] * i0);
        *(float2*)&g_O[((size_t)(b * S_ + r + 8) * HID_) + h * HD_ + c] =
            make_float2(acc_o[nt2][2] * i1, acc_o[nt2][3] * i1);
    }
}

// ---- out-proj GEMM (hi/lo split): C = (Ah+Al)@(Bh+Bl)^T + bias ----
__global__ __launch_bounds__(256)
void gemm3_kernel(const __nv_bfloat16* __restrict__ Ah, const __nv_bfloat16* __restrict__ Al,
                  const __nv_bfloat16* __restrict__ Bh, const __nv_bfloat16* __restrict__ Bl,
                  const float* __restrict__ bias, float* __restrict__ C, int N, int K)
{
    extern __shared__ char smem[];
    const int brow = blockIdx.y * 128, bcol = blockIdx.x * 128;
    float acc[4][4][4]; ACC_ZERO(acc);
    mma_core<3, 2>(acc, Ah + (size_t)brow * K, Al + (size_t)brow * K,
                   Bh + (size_t)bcol * K, Bl + (size_t)bcol * K, K, K, K, smem);
    const int lane = threadIdx.x & 31, warp = threadIdx.x >> 5;
    const int wm = (warp >> 2) * 64, wn = (warp & 3) * 32;
    #pragma unroll
    for (int mi = 0; mi < 4; mi++)
        #pragma unroll
        for (int ni = 0; ni < 4; ni++) {
            int r = brow + wm + mi * 16 + (lane >> 2);
            int c = bcol + wn + ni * 8 + (lane & 3) * 2;
            float bx = bias[c], by = bias[c + 1];
            *(float2*)&C[(size_t)r * N + c]       = make_float2(acc[mi][ni][0] + bx, acc[mi][ni][1] + by);
            *(float2*)&C[(size_t)(r + 8) * N + c] = make_float2(acc[mi][ni][2] + bx, acc[mi][ni][3] + by);
        }
}

// ---------------- small kernels ----------------
__device__ __forceinline__ void split_store(float v, __nv_bfloat16* h, __nv_bfloat16* l, size_t i){
    __nv_bfloat16 hi = __float2bfloat16(v);
    h[i] = hi;
    l[i] = __float2bfloat16(v - __bfloat162float(hi));
}

__global__ void copy_x_kernel(const float* __restrict__ x){
    size_t i = (size_t)blockIdx.x * blockDim.x + threadIdx.x;
    float4 v = ((const float4*)x)[i];
    ((float4*)g_cur)[i] = v;
    size_t e = i * 4;
    split_store(v.x, g_curh, g_curl, e + 0);
    split_store(v.y, g_curh, g_curl, e + 1);
    split_store(v.z, g_curh, g_curl, e + 2);
    split_store(v.w, g_curh, g_curl, e + 3);
}

__global__ void wt_kernel(const float* __restrict__ src,
                          __nv_bfloat16* __restrict__ dh, __nv_bfloat16* __restrict__ dl,
                          int K, int N)
{
    __shared__ float t[32][33];
    const int n0 = blockIdx.x * 32, k0 = blockIdx.y * 32;
    const int tx = threadIdx.x, ty = threadIdx.y;
    for (int i = ty; i < 32; i += 8)
        t[i][tx] = src[(size_t)(k0 + i) * N + n0 + tx];
    __syncthreads();
    for (int i = ty; i < 32; i += 8)
        split_store(t[tx][i], dh, dl, (size_t)(n0 + i) * K + k0 + tx);
}

// cur += (O @ W_pinv + b_pinv) @ Wa + ba ; refresh hi/lo
__global__ void update_kernel(const float* __restrict__ W_pinv, const float* __restrict__ b_pinv,
                              const float* __restrict__ Wa, const float* __restrict__ ba)
{
    const int row = blockIdx.x, tid = threadIdx.x;
    const int warp = tid >> 5, lane = tid & 31;
    const float* orow = g_O + (size_t)row * HID_;
    __shared__ float m[MD_];
    float acc = 0.f;
    for (int i = lane; i < HID_; i += 32)
        acc += orow[i] * W_pinv[i * MD_ + warp];
    #pragma unroll
    for (int o = 16; o > 0; o >>= 1) acc += __shfl_xor_sync(0xffffffffu, acc, o);
    if (lane == 0) m[warp] = acc + b_pinv[warp];
    __syncthreads();
    float mv[MD_];
    #pragma unroll
    for (int j = 0; j < MD_; j++) mv[j] = m[j];
    #pragma unroll
    for (int t = 0; t < HID_ / 256; t++) {
        int col = tid + t * 256;
        float u = ba[col];
        #pragma unroll
        for (int j = 0; j < MD_; j++) u += mv[j] * Wa[j * HID_ + col];
        size_t idx = (size_t)row * HID_ + col;
        float nc = g_cur[idx] + u;
        g_cur[idx] = nc;
        split_store(nc, g_curh, g_curl, idx);
    }
}

// ---------------- launcher ----------------
extern "C" void kernel_launch(void* const* d_in, const int* in_sizes, int n_in,
                              void* d_out, int out_size)
{
    const float* x      = (const float*)d_in[0];
    const float* W_qkv  = (const float*)d_in[1];
    const float* b_qkv  = (const float*)d_in[2];
    const float* W_pinv = (const float*)d_in[3];
    const float* b_pinv = (const float*)d_in[4];
    const float* W_attn = (const float*)d_in[5];
    const float* b_attn = (const float*)d_in[6];
    const float* W_out  = (const float*)d_in[7];
    const float* b_out  = (const float*)d_in[8];
    float* out = (float*)d_out;

    const int SM1 = 3 * 2 * 128 * 80;   // 61440 (gemm_qkv, 3-stage; staging 37376 fits)
    const int SM3 = 2 * 4 * 128 * 80;   // 81920 (gemm3, 2-stage)
    const int SMF = 106496;             // flash (2 CTAs/SM)
    cudaFuncSetAttribute(gemm_qkv_kernel, cudaFuncAttributeMaxDynamicSharedMemorySize, SM1);
    cudaFuncSetAttribute(gemm3_kernel,    cudaFuncAttributeMaxDynamicSharedMemorySize, SM3);
    cudaFuncSetAttribute(flash_kernel,    cudaFuncAttributeMaxDynamicSharedMemorySize, SMF);

    __nv_bfloat16 *curh = nullptr, *curl = nullptr, *wqh = nullptr, *wql = nullptr,
                  *woh = nullptr, *wol = nullptr;
    cudaGetSymbolAddress((void**)&curh, g_curh);
    cudaGetSymbolAddress((void**)&curl, g_curl);
    cudaGetSymbolAddress((void**)&wqh,  g_Wqh);
    cudaGetSymbolAddress((void**)&wql,  g_Wql);
    cudaGetSymbolAddress((void**)&woh,  g_Woh);
    cudaGetSymbolAddress((void**)&wol,  g_Wol);

    copy_x_kernel<<<(M_ * HID_) / 4 / 256, 256>>>(x);
    wt_kernel<<<dim3(3 * HID_ / 32, HID_ / 32), dim3(32, 8)>>>(W_qkv, wqh, wql, HID_, 3 * HID_);
    wt_kernel<<<dim3(HID_ / 32, HID_ / 32), dim3(32, 8)>>>(W_out, woh, wol, HID_, HID_);

    for (int l = 0; l < L_; ++l) {
        gemm_qkv_kernel<<<dim3(24, 64), 256, SM1>>>(curh, wqh, b_qkv);
        flash_kernel<<<dim3(8, BH_), 256, SMF>>>();
        update_kernel<<<M_, 256>>>(W_pinv, b_pinv,
                                   W_attn + (size_t)l * MD_ * HID_,
                                   b_attn + (size_t)l * HID_);
    }

    gemm3_kernel<<<dim3(HID_ / 128, M_ / 128), 256, SM3>>>(
        curh, curl, woh, wol, b_out, out, HID_, HID_);
}

// round 12
// speedup vs baseline: 6.1393x; 1.1295x over previous
#include <cuda_runtime.h>
#include <cuda_bf16.h>
#include <cstdint>
#include <math.h>

#define B_    8
#define S_    1024
#define HID_  1024
#define H_    8
#define HD_   128
#define MD_   8
#define L_    3
#define M_    (B_*S_)
#define BH_   (B_*H_)
#define EPS_  1e-7f
#define INV_SQRT_D 0.08838834764831845f

// ---------------- PTX helpers (plain sm_80+ features only) ----------------
__device__ __forceinline__ uint32_t smem_u32(const void* p){
    uint32_t a;
    asm("{ .reg .u64 t; cvta.to.shared.u64 t, %1; cvt.u32.u64 %0, t; }" : "=r"(a) : "l"(p));
    return a;
}
#define CPA(sa, gp) \
    asm volatile("cp.async.cg.shared.global [%0], [%1], 16;" \
        :: "r"(sa), "l"(__cvta_generic_to_global((const void*)(gp))) : "memory")
#define CP_COMMIT() asm volatile("cp.async.commit_group;" ::: "memory")
#define CP_WAIT2()  asm volatile("cp.async.wait_group 2;" ::: "memory")
#define CP_WAIT1()  asm volatile("cp.async.wait_group 1;" ::: "memory")
#define CP_WAIT0()  asm volatile("cp.async.wait_group 0;" ::: "memory")

#define LDSM4(r, addr) \
    asm volatile("ldmatrix.sync.aligned.m8n8.x4.shared.b16 {%0,%1,%2,%3}, [%4];" \
        : "=r"((r)[0]), "=r"((r)[1]), "=r"((r)[2]), "=r"((r)[3]) : "r"(addr))

#define MMA_B16(c, a0,a1,a2,a3, b0,b1) \
    asm volatile("mma.sync.aligned.m16n8k16.row.col.f32.bf16.bf16.f32 " \
        "{%0,%1,%2,%3}, {%4,%5,%6,%7}, {%8,%9}, {%0,%1,%2,%3};" \
        : "+f"((c)[0]), "+f"((c)[1]), "+f"((c)[2]), "+f"((c)[3]) \
        : "r"(a0), "r"(a1), "r"(a2), "r"(a3), "r"(b0), "r"(b1))

__device__ __forceinline__ uint32_t pack_bf2(float a, float b){
    __nv_bfloat162 t = __floats2bfloat162_rn(a, b);
    return *(uint32_t*)&t;
}

// ---------------- scratch ----------------
__device__ float          g_cur [(size_t)M_ * HID_];
__device__ __nv_bfloat16  g_curh[(size_t)M_ * HID_];
__device__ __nv_bfloat16  g_curl[(size_t)M_ * HID_];
__device__ __nv_bfloat16  g_Wqh [(size_t)3 * HID_ * HID_];   // W_qkv^T bf16 [3072,1024]
__device__ __nv_bfloat16  g_Wql [(size_t)3 * HID_ * HID_];
__device__ __nv_bfloat16  g_Woh [(size_t)HID_ * HID_];       // W_out^T hi
__device__ __nv_bfloat16  g_Wol [(size_t)HID_ * HID_];       // W_out^T lo
__device__ __nv_bfloat16  g_Qb  [(size_t)BH_ * S_ * HD_];    // expmapped q * inv_sqrt_d
__device__ __nv_bfloat16  g_Kb  [(size_t)BH_ * S_ * HD_];    // expmapped k
__device__ __nv_bfloat16  g_Vt  [(size_t)BH_ * HD_ * S_];    // V^T [z, d, s]
__device__ float          g_mp  [(size_t)M_ * H_ * MD_];     // per-head m partials [row][h][8]

// ==================================================================
// MMA core: acc += A[128,K] @ B[128,K]^T  (bf16 in, fp32 acc)
// NT=1: fragment-pipelined A loads. STAGES-deep cp.async pipeline.
// ==================================================================
template<int NT, int STAGES>
__device__ __forceinline__ void mma_core(
    float (&acc)[4][4][4],
    const __nv_bfloat16* __restrict__ Ah, const __nv_bfloat16* __restrict__ Al,
    const __nv_bfloat16* __restrict__ Bh, const __nv_bfloat16* __restrict__ Bl,
    int ldA, int ldB, int K, char* smem)
{
    constexpr int TILE = 128 * 80;
    constexpr int NS   = (NT == 3) ? 4 : 2;
    constexpr int STG  = NS * TILE;
    const int tid  = threadIdx.x;
    const int lane = tid & 31, warp = tid >> 5;
    const int wm = (warp >> 2) * 64;
    const int wn = (warp & 3) * 32;
    const uint32_t sb = smem_u32(smem);

    auto issue = [&](int stage, int k0) {
        #pragma unroll
        for (int i = 0; i < 2; i++) {
            int q = tid + i * 256;
            int r = q >> 2, c = q & 3;
            uint32_t sa = sb + stage * STG + r * 80 + c * 16;
            CPA(sa,                              Ah + (size_t)r * ldA + k0 + c * 8);
            CPA(sa + (NT == 3 ? 2 : 1) * TILE,   Bh + (size_t)r * ldB + k0 + c * 8);
            if (NT == 3) {
                CPA(sa + TILE,                   Al + (size_t)r * ldA + k0 + c * 8);
                CPA(sa + 3 * TILE,               Bl + (size_t)r * ldB + k0 + c * 8);
            }
        }
        CP_COMMIT();
    };

    #pragma unroll
    for (int s = 0; s < STAGES - 1; s++) issue(s, s * 32);

    const int T = K / 32;
    for (int kt = 0; kt < T; kt++) {
        int rem;
        if (kt + STAGES - 1 < T) {
            issue((kt + STAGES - 1) % STAGES, (kt + STAGES - 1) * 32);
            rem = STAGES - 1;
        } else {
            rem = T - 1 - kt;
        }
        if (rem >= 2) CP_WAIT2(); else if (rem == 1) CP_WAIT1(); else CP_WAIT0();
        __syncthreads();
        const uint32_t ab = sb + (kt % STAGES) * STG;
        const uint32_t bb = ab + (NT == 3 ? 2 : 1) * TILE;
        #pragma unroll
        for (int kk = 0; kk < 2; kk++) {
            const uint32_t roff = (uint32_t)(lane & 15) * 80 + (2 * kk + (lane >> 4)) * 16;
            uint32_t bh[8], bl[8];
            LDSM4(bh,     bb + (uint32_t)wn * 80 + roff);
            LDSM4(bh + 4, bb + (uint32_t)(wn + 16) * 80 + roff);
            if (NT == 3) {
                LDSM4(bl,     bb + TILE + (uint32_t)wn * 80 + roff);
                LDSM4(bl + 4, bb + TILE + (uint32_t)(wn + 16) * 80 + roff);
                #pragma unroll
                for (int mi = 0; mi < 4; mi++) {
                    uint32_t ah[4], al[4];
                    const uint32_t abase = ab + (uint32_t)(wm + mi * 16) * 80 + roff;
                    LDSM4(ah, abase);
                    LDSM4(al, abase + TILE);
                    #pragma unroll
                    for (int ni = 0; ni < 4; ni++) {
                        const int p = (ni >> 1) * 4, s = ni & 1;
                        uint32_t b0 = bh[p + s], b1 = bh[p + 2 + s];
                        uint32_t d0 = bl[p + s], d1 = bl[p + 2 + s];
                        MMA_B16(acc[mi][ni], ah[0], ah[1], ah[2], ah[3], b0, b1);
                        MMA_B16(acc[mi][ni], ah[0], ah[1], ah[2], ah[3], d0, d1);
                        MMA_B16(acc[mi][ni], al[0], al[1], al[2], al[3], b0, b1);
                    }
                }
            } else {
                // fragment-pipelined A: load mi+1 while computing mi
                uint32_t a0[4], a1[4];
                LDSM4(a0, ab + (uint32_t)wm * 80 + roff);
                #pragma unroll
                for (int mi = 0; mi < 4; mi++) {
                    uint32_t* cur = (mi & 1) ? a1 : a0;
                    uint32_t* nxt = (mi & 1) ? a0 : a1;
                    if (mi < 3)
                        LDSM4(nxt, ab + (uint32_t)(wm + (mi + 1) * 16) * 80 + roff);
                    #pragma unroll
                    for (int ni = 0; ni < 4; ni++) {
                        const int p = (ni >> 1) * 4, s = ni & 1;
                        MMA_B16(acc[mi][ni], cur[0], cur[1], cur[2], cur[3],
                                bh[p + s], bh[p + 2 + s]);
                    }
                }
            }
        }
        __syncthreads();
    }
}

#define ACC_ZERO(acc) \
    _Pragma("unroll") for (int _i = 0; _i < 4; _i++) \
    _Pragma("unroll") for (int _j = 0; _j < 4; _j++) \
    _Pragma("unroll") for (int _k = 0; _k < 4; _k++) (acc)[_i][_j][_k] = 0.f;

// ==================================================================
// Fused QKV GEMM: one CTA column tile == one head.
// part 0/1 (q/k): expmap0 epilogue (+1/sqrt(d) on q) -> bf16 [z,s,d]
// part 2 (v): transpose epilogue -> bf16 Vt [z,d,s]
// grid (24, 64), smem = 3*2*10240 = 61440
// ==================================================================
__global__ __launch_bounds__(256, 2)
void gemm_qkv_kernel(const __nv_bfloat16* __restrict__ A,
                     const __nv_bfloat16* __restrict__ Bw,
                     const float* __restrict__ bias)
{
    extern __shared__ char smem[];
    const int bx = blockIdx.x;
    const int part = bx >> 3, h = bx & 7;
    const int brow = blockIdx.y * 128;
    const int b = blockIdx.y >> 3, s0 = (blockIdx.y & 7) * 128;
    const int z = b * H_ + h;

    float acc[4][4][4]; ACC_ZERO(acc);
    mma_core<1, 3>(acc, A + (size_t)brow * HID_, nullptr,
                   Bw + (size_t)(bx * 128) * HID_, nullptr, HID_, HID_, HID_, smem);

    const int tid = threadIdx.x;
    const int lane = tid & 31, warp = tid >> 5;
    const int wm = (warp >> 2) * 64, wn = (warp & 3) * 32;

    // add bias
    #pragma unroll
    for (int mi = 0; mi < 4; mi++)
        #pragma unroll
        for (int ni = 0; ni < 4; ni++) {
            int gc = bx * 128 + wn + ni * 8 + (lane & 3) * 2;
            acc[mi][ni][0] += bias[gc];     acc[mi][ni][1] += bias[gc + 1];
            acc[mi][ni][2] += bias[gc];     acc[mi][ni][3] += bias[gc + 1];
        }

    __nv_bfloat16* stb = (__nv_bfloat16*)smem;       // 128 x 136 bf16 staging
    float* red = (float*)(smem + 34816);             // [128][4]
    float* scs = (float*)(smem + 36864);             // [128]

    if (part < 2) {
        // per-row sum of squares -> cross-warp reduce -> tanh(n)/n
        #pragma unroll
        for (int mi = 0; mi < 4; mi++) {
            int ra = wm + mi * 16 + (lane >> 2), rb = ra + 8;
            float ssa = 0.f, ssb = 0.f;
            #pragma unroll
            for (int ni = 0; ni < 4; ni++) {
                ssa += acc[mi][ni][0]*acc[mi][ni][0] + acc[mi][ni][1]*acc[mi][ni][1];
                ssb += acc[mi][ni][2]*acc[mi][ni][2] + acc[mi][ni][3]*acc[mi][ni][3];
            }
            ssa += __shfl_xor_sync(0xffffffffu, ssa, 1);
            ssa += __shfl_xor_sync(0xffffffffu, ssa, 2);
            ssb += __shfl_xor_sync(0xffffffffu, ssb, 1);
            ssb += __shfl_xor_sync(0xffffffffu, ssb, 2);
            if ((lane & 3) == 0) {
                red[ra * 4 + (warp & 3)] = ssa;
                red[rb * 4 + (warp & 3)] = ssb;
            }
        }
        __syncthreads();
        if (tid < 128) {
            float t = red[tid*4] + red[tid*4+1] + red[tid*4+2] + red[tid*4+3];
            float n = fmaxf(sqrtf(t), EPS_);
            float sc = tanhf(n) / n;
            if (part == 0) sc *= INV_SQRT_D;
            scs[tid] = sc;
        }
        __syncthreads();
        #pragma unroll
        for (int mi = 0; mi < 4; mi++) {
            int ra = wm + mi * 16 + (lane >> 2), rb = ra + 8;
            float sa = scs[ra], sb2 = scs[rb];
            #pragma unroll
            for (int ni = 0; ni < 4; ni++) {
                int c = wn + ni * 8 + (lane & 3) * 2;
                *(__nv_bfloat162*)&stb[ra * 136 + c] =
                    __floats2bfloat162_rn(acc[mi][ni][0]*sa, acc[mi][ni][1]*sa);
                *(__nv_bfloat162*)&stb[rb * 136 + c] =
                    __floats2bfloat162_rn(acc[mi][ni][2]*sb2, acc[mi][ni][3]*sb2);
            }
        }
        __syncthreads();
        __nv_bfloat16* dst = (part ? g_Kb : g_Qb) + ((size_t)z * S_ + s0) * HD_;
        #pragma unroll
        for (int k = 0; k < 16; k++) {
            int ch = tid + k * 256;
            int outer = ch >> 5, in4 = (ch & 31) * 4;
            *(uint2*)(dst + (size_t)outer * HD_ + in4) = *(uint2*)&stb[outer * 136 + in4];
        }
    } else {
        // V: transposed staging (outer = d, inner = s)
        #pragma unroll
        for (int mi = 0; mi < 4; mi++) {
            int ra = wm + mi * 16 + (lane >> 2), rb = ra + 8;
            #pragma unroll
            for (int ni = 0; ni < 4; ni++) {
                int c = wn + ni * 8 + (lane & 3) * 2;
                stb[c * 136 + ra]       = __float2bfloat16(acc[mi][ni][0]);
                stb[(c + 1) * 136 + ra] = __float2bfloat16(acc[mi][ni][1]);
                stb[c * 136 + rb]       = __float2bfloat16(acc[mi][ni][2]);
                stb[(c + 1) * 136 + rb] = __float2bfloat16(acc[mi][ni][3]);
            }
        }
        __syncthreads();
        __nv_bfloat16* dst = g_Vt + (size_t)z * HD_ * S_ + s0;
        #pragma unroll
        for (int k = 0; k < 16; k++) {
            int ch = tid + k * 256;
            int outer = ch >> 5, in4 = (ch & 31) * 4;
            *(uint2*)(dst + (size_t)outer * S_ + in4) = *(uint2*)&stb[outer * 136 + in4];
        }
    }
}

// ==================================================================
// Flash attention, KB=64 K-blocks, 2 CTAs/SM.
// Epilogue computes m-partials = (O/l) @ W_pinv[h-slice] directly
// (O is consumed ONLY by the MD=8 projection) -> g_mp[row][h][8].
// grid (8, 64), 256 threads, smem = 106496 B.
// ==================================================================
#define STRQ 272   // Q/K row: 128 bf16 + 16B pad
#define STRV 144   // V row: 64 bf16 + 16B pad
__global__ __launch_bounds__(256, 2)
void flash_kernel(const float* __restrict__ W_pinv)
{
    extern __shared__ char smem[];
    const int qb = blockIdx.x, z = blockIdx.y;
    const int b = z >> 3, h = z & 7;
    const int tid = threadIdx.x, lane = tid & 31, warp = tid >> 5;
    const uint32_t sb = smem_u32(smem);
    const uint32_t Qs = sb;
    const uint32_t Ks[2] = { sb + 34816u,  sb + 70656u };
    const uint32_t Vs[2] = { sb + 52224u,  sb + 88064u };

    const __nv_bfloat16* Qg = g_Qb + ((size_t)z * S_ + qb * 128) * HD_;
    const __nv_bfloat16* Kg = g_Kb + (size_t)z * S_ * HD_;
    const __nv_bfloat16* Vg = g_Vt + (size_t)z * HD_ * S_;

    auto issueKV = [&](int buf, int kb) {
        #pragma unroll
        for (int i = 0; i < 4; i++) {              // K: 64 rows x 16 chunks
            int ch = tid + i * 256;
            int r = ch >> 4, c = ch & 15;
            CPA(Ks[buf] + r * STRQ + c * 16, Kg + (size_t)(kb * 64 + r) * HD_ + c * 8);
        }
        #pragma unroll
        for (int i = 0; i < 4; i++) {              // V: 128 rows x 8 chunks
            int ch = tid + i * 256;
            int r = ch >> 3, c = ch & 7;
            CPA(Vs[buf] + r * STRV + c * 16, Vg + (size_t)r * S_ + kb * 64 + c * 8);
        }
        CP_COMMIT();
    };

    #pragma unroll
    for (int i = 0; i < 8; i++) {
        int ch = tid + i * 256;
        int r = ch >> 4, c = ch & 15;
        CPA(Qs + r * STRQ + c * 16, Qg + (size_t)r * HD_ + c * 8);
    }
    issueKV(0, 0);          // Q + K0 + V0 as group 0
    issueKV(1, 1);          // group 1

    float acc_o[16][4];
    #pragma unroll
    for (int i = 0; i < 16; i++)
        #pragma unroll
        for (int j = 0; j < 4; j++) acc_o[i][j] = 0.f;
    float l0 = 0.f, l1 = 0.f;

    for (int kb = 0; kb < 16; kb++) {
        if (kb < 15) CP_WAIT1(); else CP_WAIT0();
        __syncthreads();
        const int buf = kb & 1;
        const uint32_t Kb = Ks[buf], Vb = Vs[buf];

        float acc_s[8][4];
        #pragma unroll
        for (int i = 0; i < 8; i++)
            #pragma unroll
            for (int j = 0; j < 4; j++) acc_s[i][j] = 0.f;

        #pragma unroll
        for (int ks = 0; ks < 8; ks++) {
            const uint32_t roff = (uint32_t)(lane & 15) * STRQ + (2 * ks + (lane >> 4)) * 16;
            uint32_t aq[4];
            LDSM4(aq, Qs + (uint32_t)(warp * 16) * STRQ + roff);
            #pragma unroll
            for (int nt = 0; nt < 4; nt++) {
                uint32_t bh[4];
                LDSM4(bh, Kb + (uint32_t)(nt * 16) * STRQ + roff);
                MMA_B16(acc_s[2 * nt],     aq[0], aq[1], aq[2], aq[3], bh[0], bh[2]);
                MMA_B16(acc_s[2 * nt + 1], aq[0], aq[1], aq[2], aq[3], bh[1], bh[3]);
            }
        }

        uint32_t Af[4][4];
        #pragma unroll
        for (int nt2 = 0; nt2 < 8; nt2++) {
            float e0 = __expf(acc_s[nt2][0]);
            float e1 = __expf(acc_s[nt2][1]);
            float e2 = __expf(acc_s[nt2][2]);
            float e3 = __expf(acc_s[nt2][3]);
            l0 += e0 + e1;
            l1 += e2 + e3;
            int kt = nt2 >> 1, hf = (nt2 & 1) * 2;
            Af[kt][hf]     = pack_bf2(e0, e1);
            Af[kt][hf + 1] = pack_bf2(e2, e3);
        }

        #pragma unroll
        for (int kt = 0; kt < 4; kt++) {
            const uint32_t roff = (uint32_t)(lane & 15) * STRV + (2 * kt + (lane >> 4)) * 16;
            #pragma unroll
            for (int nt = 0; nt < 8; nt++) {
                uint32_t bv[4];
                LDSM4(bv, Vb + (uint32_t)(nt * 16) * STRV + roff);
                MMA_B16(acc_o[2 * nt],     Af[kt][0], Af[kt][1], Af[kt][2], Af[kt][3], bv[0], bv[2]);
                MMA_B16(acc_o[2 * nt + 1], Af[kt][0], Af[kt][1], Af[kt][2], Af[kt][3], bv[1], bv[3]);
            }
        }
        __syncthreads();
        if (kb + 2 < 16) issueKV(buf, kb + 2);
    }

    // row sums of exp
    l0 += __shfl_xor_sync(0xffffffffu, l0, 1);
    l0 += __shfl_xor_sync(0xffffffffu, l0, 2);
    l1 += __shfl_xor_sync(0xffffffffu, l1, 1);
    l1 += __shfl_xor_sync(0xffffffffu, l1, 2);
    const float i0 = 1.f / l0, i1 = 1.f / l1;

    // stage W_pinv[h*128 .. h*128+127][0..8) into smem (padded [128][9])
    __syncthreads();
    float* wp = (float*)smem;
    #pragma unroll
    for (int i = 0; i < 4; i++) {
        int idx = tid + i * 256;          // 1024 entries
        int c = idx >> 3, j = idx & 7;
        wp[c * 9 + j] = W_pinv[(size_t)(h * HD_ + c) * MD_ + j];
    }
    __syncthreads();

    // m-partials: pm[row][j] = sum_c (O[row][c]/l) * Wp[c][j]
    float pm0[MD_], pm1[MD_];
    #pragma unroll
    for (int j = 0; j < MD_; j++) { pm0[j] = 0.f; pm1[j] = 0.f; }
    #pragma unroll
    for (int nt2 = 0; nt2 < 16; nt2++) {
        int c = nt2 * 8 + (lane & 3) * 2;
        float o0 = acc_o[nt2][0] * i0, o1 = acc_o[nt2][1] * i0;
        float o2 = acc_o[nt2][2] * i1, o3 = acc_o[nt2][3] * i1;
        #pragma unroll
        for (int j = 0; j < MD_; j++) {
            pm0[j] += o0 * wp[c * 9 + j] + o1 * wp[(c + 1) * 9 + j];
            pm1[j] += o2 * wp[c * 9 + j] + o3 * wp[(c + 1) * 9 + j];
        }
    }
    #pragma unroll
    for (int j = 0; j < MD_; j++) {
        pm0[j] += __shfl_xor_sync(0xffffffffu, pm0[j], 1);
        pm0[j] += __shfl_xor_sync(0xffffffffu, pm0[j], 2);
        pm1[j] += __shfl_xor_sync(0xffffffffu, pm1[j], 1);
        pm1[j] += __shfl_xor_sync(0xffffffffu, pm1[j], 2);
    }
    if ((lane & 3) == 0) {
        int s = qb * 128 + warp * 16 + (lane >> 2);
        float* d0 = g_mp + ((size_t)(b * S_ + s) * H_ + h) * MD_;
        float* d1 = g_mp + ((size_t)(b * S_ + s + 8) * H_ + h) * MD_;
        *(float4*)(d0)     = make_float4(pm0[0], pm0[1], pm0[2], pm0[3]);
        *(float4*)(d0 + 4) = make_float4(pm0[4], pm0[5], pm0[6], pm0[7]);
        *(float4*)(d1)     = make_float4(pm1[0], pm1[1], pm1[2], pm1[3]);
        *(float4*)(d1 + 4) = make_float4(pm1[4], pm1[5], pm1[6], pm1[7]);
    }
}

// ---- out-proj GEMM (hi/lo split): C = (Ah+Al)@(Bh+Bl)^T + bias ----
__global__ __launch_bounds__(256, 2)
void gemm3_kernel(const __nv_bfloat16* __restrict__ Ah, const __nv_bfloat16* __restrict__ Al,
                  const __nv_bfloat16* __restrict__ Bh, const __nv_bfloat16* __restrict__ Bl,
                  const float* __restrict__ bias, float* __restrict__ C, int N, int K)
{
    extern __shared__ char smem[];
    const int brow = blockIdx.y * 128, bcol = blockIdx.x * 128;
    float acc[4][4][4]; ACC_ZERO(acc);
    mma_core<3, 2>(acc, Ah + (size_t)brow * K, Al + (size_t)brow * K,
                   Bh + (size_t)bcol * K, Bl + (size_t)bcol * K, K, K, K, smem);
    const int lane = threadIdx.x & 31, warp = threadIdx.x >> 5;
    const int wm = (warp >> 2) * 64, wn = (warp & 3) * 32;
    #pragma unroll
    for (int mi = 0; mi < 4; mi++)
        #pragma unroll
        for (int ni = 0; ni < 4; ni++) {
            int r = brow + wm + mi * 16 + (lane >> 2);
            int c = bcol + wn + ni * 8 + (lane & 3) * 2;
            float bx = bias[c], by = bias[c + 1];
            *(float2*)&C[(size_t)r * N + c]       = make_float2(acc[mi][ni][0] + bx, acc[mi][ni][1] + by);
            *(float2*)&C[(size_t)(r + 8) * N + c] = make_float2(acc[mi][ni][2] + bx, acc[mi][ni][3] + by);
        }
}

// ---------------- small kernels ----------------
__device__ __forceinline__ void split_store(float v, __nv_bfloat16* h, __nv_bfloat16* l, size_t i){
    __nv_bfloat16 hi = __float2bfloat16(v);
    h[i] = hi;
    l[i] = __float2bfloat16(v - __bfloat162float(hi));
}

__global__ void copy_x_kernel(const float* __restrict__ x){
    size_t i = (size_t)blockIdx.x * blockDim.x + threadIdx.x;
    float4 v = ((const float4*)x)[i];
    ((float4*)g_cur)[i] = v;
    size_t e = i * 4;
    split_store(v.x, g_curh, g_curl, e + 0);
    split_store(v.y, g_curh, g_curl, e + 1);
    split_store(v.z, g_curh, g_curl, e + 2);
    split_store(v.w, g_curh, g_curl, e + 3);
}

__global__ void wt_kernel(const float* __restrict__ src,
                          __nv_bfloat16* __restrict__ dh, __nv_bfloat16* __restrict__ dl,
                          int K, int N)
{
    __shared__ float t[32][33];
    const int n0 = blockIdx.x * 32, k0 = blockIdx.y * 32;
    const int tx = threadIdx.x, ty = threadIdx.y;
    for (int i = ty; i < 32; i += 8)
        t[i][tx] = src[(size_t)(k0 + i) * N + n0 + tx];
    __syncthreads();
    for (int i = ty; i < 32; i += 8)
        split_store(t[tx][i], dh, dl, (size_t)(n0 + i) * K + k0 + tx);
}

// cur += (sum_h mp[row][h] + b_pinv) @ Wa + ba ; refresh hi/lo
__global__ void update_kernel(const float* __restrict__ b_pinv,
                              const float* __restrict__ Wa, const float* __restrict__ ba)
{
    const int row = blockIdx.x, tid = threadIdx.x;
    __shared__ float m[MD_];
    if (tid < MD_) {
        const float* mp = g_mp + (size_t)row * H_ * MD_;
        float s = b_pinv[tid];
        #pragma unroll
        for (int hh = 0; hh < H_; hh++) s += mp[hh * MD_ + tid];
        m[tid] = s;
    }
    __syncthreads();
    float mv[MD_];
    #pragma unroll
    for (int j = 0; j < MD_; j++) mv[j] = m[j];
    #pragma unroll
    for (int t = 0; t < HID_ / 256; t++) {
        int col = tid + t * 256;
        float u = ba[col];
        #pragma unroll
        for (int j = 0; j < MD_; j++) u += mv[j] * Wa[j * HID_ + col];
        size_t idx = (size_t)row * HID_ + col;
        float nc = g_cur[idx] + u;
        g_cur[idx] = nc;
        split_store(nc, g_curh, g_curl, idx);
    }
}

// ---------------- launcher ----------------
extern "C" void kernel_launch(void* const* d_in, const int* in_sizes, int n_in,
                              void* d_out, int out_size)
{
    const float* x      = (const float*)d_in[0];
    const float* W_qkv  = (const float*)d_in[1];
    const float* b_qkv  = (const float*)d_in[2];
    const float* W_pinv = (const float*)d_in[3];
    const float* b_pinv = (const float*)d_in[4];
    const float* W_attn = (const float*)d_in[5];
    const float* b_attn = (const float*)d_in[6];
    const float* W_out  = (const float*)d_in[7];
    const float* b_out  = (const float*)d_in[8];
    float* out = (float*)d_out;

    const int SM1 = 3 * 2 * 128 * 80;   // 61440 (gemm_qkv, 3-stage)
    const int SM3 = 2 * 4 * 128 * 80;   // 81920 (gemm3, 2-stage)
    const int SMF = 106496;             // flash (2 CTAs/SM)
    cudaFuncSetAttribute(gemm_qkv_kernel, cudaFuncAttributeMaxDynamicSharedMemorySize, SM1);
    cudaFuncSetAttribute(gemm3_kernel,    cudaFuncAttributeMaxDynamicSharedMemorySize, SM3);
    cudaFuncSetAttribute(flash_kernel,    cudaFuncAttributeMaxDynamicSharedMemorySize, SMF);

    __nv_bfloat16 *curh = nullptr, *curl = nullptr, *wqh = nullptr, *wql = nullptr,
                  *woh = nullptr, *wol = nullptr;
    cudaGetSymbolAddress((void**)&curh, g_curh);
    cudaGetSymbolAddress((void**)&curl, g_curl);
    cudaGetSymbolAddress((void**)&wqh,  g_Wqh);
    cudaGetSymbolAddress((void**)&wql,  g_Wql);
    cudaGetSymbolAddress((void**)&woh,  g_Woh);
    cudaGetSymbolAddress((void**)&wol,  g_Wol);

    copy_x_kernel<<<(M_ * HID_) / 4 / 256, 256>>>(x);
    wt_kernel<<<dim3(3 * HID_ / 32, HID_ / 32), dim3(32, 8)>>>(W_qkv, wqh, wql, HID_, 3 * HID_);
    wt_kernel<<<dim3(HID_ / 32, HID_ / 32), dim3(32, 8)>>>(W_out, woh, wol, HID_, HID_);

    for (int l = 0; l < L_; ++l) {
        gemm_qkv_kernel<<<dim3(24, 64), 256, SM1>>>(curh, wqh, b_qkv);
        flash_kernel<<<dim3(8, BH_), 256, SMF>>>(W_pinv);
        update_kernel<<<M_, 256>>>(b_pinv,
                                   W_attn + (size_t)l * MD_ * HID_,
                                   b_attn + (size_t)l * HID_);
    }

    gemm3_kernel<<<dim3(HID_ / 128, M_ / 128), 256, SM3>>>(
        curh, curl, woh, wol, b_out, out, HID_, HID_);
}